// round 5
// baseline (speedup 1.0000x reference)
#include <cuda_runtime.h>
#include <cuda_bf16.h>
#include <cstdint>
#include <cstddef>

#define HN     16
#define DMODEL 1024
#define NSEQ   2048
#define NB     2
#define HD     64
#define LN_EPS 1e-5f

typedef unsigned long long u64;

// ---------------- scratch (device globals; no allocation allowed) ----------
__device__ float g_q [(size_t)NB * NSEQ * DMODEL];        // 16.8 MB
__device__ float g_kv[(size_t)NB * NSEQ * 2048];          // 33.5 MB (k | v)
__device__ float g_vt[(size_t)NB * DMODEL * NSEQ];        // 16.8 MB v transposed
__device__ float g_E [(size_t)NB * HN * NSEQ * NSEQ];     // 537 MB exp(scores) -> aw
__device__ float g_rowsum[NB * HN * NSEQ];

// -------------------- packed f32x2 helpers (talkln) ------------------------
__device__ __forceinline__ u64 bcast2(float x) {
    u64 r;
    unsigned u = __float_as_uint(x);
    asm("mov.b64 %0, {%1, %1};" : "=l"(r) : "r"(u));
    return r;
}
__device__ __forceinline__ void fma2(u64& d, u64 a, u64 b) {
    asm("fma.rn.f32x2 %0, %1, %2, %0;" : "+l"(d) : "l"(a), "l"(b));
}

// ---------------- fast exp on the FMA pipe (avoid MUFU.EX2) ----------------
__device__ __forceinline__ float fast_exp(float x) {
    float t = x * 1.4426950408889634f;
    float r = rintf(t);
    float f = t - r;
    float p =      1.5403530394e-4f;
    p = fmaf(p, f, 1.3333558146e-3f);
    p = fmaf(p, f, 9.6181291076e-3f);
    p = fmaf(p, f, 5.5504108665e-2f);
    p = fmaf(p, f, 2.4022650696e-1f);
    p = fmaf(p, f, 6.9314718056e-1f);
    p = fmaf(p, f, 1.0f);
    return p * __int_as_float(((int)r + 127) << 23);
}

// ------------------------- mma.sync bf16 wrapper ----------------------------
__device__ __forceinline__ void mma16816(
    float (&c)[4], const uint32_t (&a)[4], uint32_t b0, uint32_t b1)
{
    asm volatile(
        "mma.sync.aligned.m16n8k16.row.col.f32.bf16.bf16.f32 "
        "{%0,%1,%2,%3}, {%4,%5,%6,%7}, {%8,%9}, {%0,%1,%2,%3};"
        : "+f"(c[0]), "+f"(c[1]), "+f"(c[2]), "+f"(c[3])
        : "r"(a[0]), "r"(a[1]), "r"(a[2]), "r"(a[3]), "r"(b0), "r"(b1));
}
__device__ __forceinline__ uint32_t lds32(const uint16_t* p, int off) {
    return *(const uint32_t*)(p + off);
}

// ---- decoupled staging: LDG to regs (prefetch), then convert+STS -----------
template<int ROWS>
__device__ __forceinline__ void ldg_tile(
    float4 (&r)[ROWS / 32], const float* __restrict__ src, size_t stride, int tid)
{
#pragma unroll
    for (int s = 0; s < ROWS / 32; s++) {
        int idx = s * 256 + tid;
        int row = idx >> 3;
        int cg  = idx & 7;
        r[s] = *(const float4*)(src + (size_t)row * stride + cg * 4);
    }
}
template<int ROWS>
__device__ __forceinline__ void sts_tile(
    const float4 (&r)[ROWS / 32],
    uint16_t* __restrict__ hi, uint16_t* __restrict__ lo, int tid)
{
#pragma unroll
    for (int s = 0; s < ROWS / 32; s++) {
        int idx = s * 256 + tid;
        int row = idx >> 3;
        int cg  = idx & 7;
        float4 v = r[s];
        __nv_bfloat162 h01 = __floats2bfloat162_rn(v.x, v.y);
        __nv_bfloat162 h23 = __floats2bfloat162_rn(v.z, v.w);
        float rx = v.x - __bfloat162float(__low2bfloat16(h01));
        float ry = v.y - __bfloat162float(__high2bfloat16(h01));
        float rz = v.z - __bfloat162float(__low2bfloat16(h23));
        float rw = v.w - __bfloat162float(__high2bfloat16(h23));
        __nv_bfloat162 l01 = __floats2bfloat162_rn(rx, ry);
        __nv_bfloat162 l23 = __floats2bfloat162_rn(rz, rw);
        int off = row * 36 + cg * 4;
        *(uint2*)(hi + off) = make_uint2(*(uint32_t*)&h01, *(uint32_t*)&h23);
        *(uint2*)(lo + off) = make_uint2(*(uint32_t*)&l01, *(uint32_t*)&l23);
    }
}

// ---- HMMA split-bf16 core: C[128 x NT] = A[128,K] @ B[NT,K]^T  (NT 64/128) -
// 256 threads = 8 warps (4 x 2). Warp tile 32 x (NT/2). K-chunk 32.
// Register-buffered prefetch: LDG of chunk i+1 is issued before MMAs of i.
template<int NT, bool EXP_EPI>
__device__ __forceinline__ void hmma_core(
    const float* __restrict__ A, size_t lda,
    const float* __restrict__ B, size_t ldb,
    int nk, float* __restrict__ C, size_t ldc,
    float alpha, float* __restrict__ rowsum)
{
    constexpr int NTILES = NT / 16;
    __shared__ __align__(16) uint16_t sAhi[128 * 36];
    __shared__ __align__(16) uint16_t sAlo[128 * 36];
    __shared__ __align__(16) uint16_t sBhi[NT * 36];
    __shared__ __align__(16) uint16_t sBlo[NT * 36];

    const int tid  = threadIdx.x;
    const int wid  = tid >> 5;
    const int lane = tid & 31;
    const int wm = wid & 3, wn = wid >> 2;
    const int g = lane >> 2, t = lane & 3;

    float acc[2][NTILES][4];
#pragma unroll
    for (int mt = 0; mt < 2; mt++)
#pragma unroll
        for (int nt = 0; nt < NTILES; nt++)
#pragma unroll
            for (int q = 0; q < 4; q++) acc[mt][nt][q] = 0.f;

    float4 rA[4], rB[NT / 32];
    ldg_tile<128>(rA, A, lda, tid);
    ldg_tile<NT >(rB, B, ldb, tid);
    sts_tile<128>(rA, sAhi, sAlo, tid);
    sts_tile<NT >(rB, sBhi, sBlo, tid);
    __syncthreads();

    for (int i = 0; i < nk; i++) {
        if (i + 1 < nk) {
            ldg_tile<128>(rA, A + (size_t)(i + 1) * 32, lda, tid);
            ldg_tile<NT >(rB, B + (size_t)(i + 1) * 32, ldb, tid);
        }
#pragma unroll
        for (int ks = 0; ks < 2; ks++) {
            uint32_t ah[2][4], al[2][4];
#pragma unroll
            for (int mt = 0; mt < 2; mt++) {
                int r0 = (wm * 32 + mt * 16 + g) * 36 + ks * 16 + 2 * t;
                ah[mt][0] = lds32(sAhi, r0);
                ah[mt][1] = lds32(sAhi, r0 + 8 * 36);
                ah[mt][2] = lds32(sAhi, r0 + 8);
                ah[mt][3] = lds32(sAhi, r0 + 8 * 36 + 8);
                al[mt][0] = lds32(sAlo, r0);
                al[mt][1] = lds32(sAlo, r0 + 8 * 36);
                al[mt][2] = lds32(sAlo, r0 + 8);
                al[mt][3] = lds32(sAlo, r0 + 8 * 36 + 8);
            }
#pragma unroll
            for (int nt = 0; nt < NTILES; nt++) {
                int c0 = (wn * (NT / 2) + nt * 8 + g) * 36 + ks * 16 + 2 * t;
                uint32_t bh0 = lds32(sBhi, c0), bh1 = lds32(sBhi, c0 + 8);
                uint32_t bl0 = lds32(sBlo, c0), bl1 = lds32(sBlo, c0 + 8);
#pragma unroll
                for (int mt = 0; mt < 2; mt++) {
                    mma16816(acc[mt][nt], ah[mt], bh0, bh1);
                    mma16816(acc[mt][nt], ah[mt], bl0, bl1);
                    mma16816(acc[mt][nt], al[mt], bh0, bh1);
                }
            }
        }
        __syncthreads();
        if (i + 1 < nk) {
            sts_tile<128>(rA, sAhi, sAlo, tid);
            sts_tile<NT >(rB, sBhi, sBlo, tid);
            __syncthreads();
        }
    }

    // epilogue: thread holds rows {R, R+8}, cols ncol+2t(+1) per ntile
#pragma unroll
    for (int mt = 0; mt < 2; mt++) {
        int r0 = wm * 32 + mt * 16 + g;
        float rs0 = 0.f, rs1 = 0.f;
#pragma unroll
        for (int nt = 0; nt < NTILES; nt++) {
            int col = wn * (NT / 2) + nt * 8 + 2 * t;
            float2 lo_pair, hi_pair;
            if (EXP_EPI) {
                lo_pair.x = fast_exp(acc[mt][nt][0]);
                lo_pair.y = fast_exp(acc[mt][nt][1]);
                hi_pair.x = fast_exp(acc[mt][nt][2]);
                hi_pair.y = fast_exp(acc[mt][nt][3]);
                rs0 += lo_pair.x + lo_pair.y;
                rs1 += hi_pair.x + hi_pair.y;
            } else {
                lo_pair.x = acc[mt][nt][0] * alpha;
                lo_pair.y = acc[mt][nt][1] * alpha;
                hi_pair.x = acc[mt][nt][2] * alpha;
                hi_pair.y = acc[mt][nt][3] * alpha;
            }
            *(float2*)(C + (size_t)r0 * ldc + col)       = lo_pair;
            *(float2*)(C + (size_t)(r0 + 8) * ldc + col) = hi_pair;
        }
        if (EXP_EPI) {
            rs0 += __shfl_down_sync(0xffffffffu, rs0, 1, 4);
            rs0 += __shfl_down_sync(0xffffffffu, rs0, 2, 4);
            rs1 += __shfl_down_sync(0xffffffffu, rs1, 1, 4);
            rs1 += __shfl_down_sync(0xffffffffu, rs1, 2, 4);
            if (t == 0) {
                atomicAdd(&rowsum[r0], rs0);
                atomicAdd(&rowsum[r0 + 8], rs1);
            }
        }
    }
}

// ------------------------------- wrappers ----------------------------------
__global__ void __launch_bounds__(256) gemm_hmma_kernel(
    const float* __restrict__ A, const float* __restrict__ B,
    float* __restrict__ C, int N, float alpha)
{
    int m0 = blockIdx.y << 7, n0 = blockIdx.x << 7;
    hmma_core<128, false>(A + (size_t)m0 * DMODEL, DMODEL,
                          B + (size_t)n0 * DMODEL, DMODEL, DMODEL / 32,
                          C + (size_t)m0 * N + n0, (size_t)N, alpha, nullptr);
}

__global__ void __launch_bounds__(256) scores_hmma_kernel()
{
    int bh = blockIdx.z, b = bh >> 4, h = bh & 15;
    int i0 = blockIdx.y << 7, j0 = blockIdx.x << 7;
    const float* Ap = g_q  + ((size_t)(b * NSEQ + i0)) * DMODEL + h * HD;
    const float* Bp = g_kv + ((size_t)(b * NSEQ + j0)) * 2048   + h * HD;
    float* Cb = g_E + (size_t)bh * NSEQ * NSEQ + (size_t)i0 * NSEQ + j0;
    hmma_core<128, true>(Ap, DMODEL, Bp, 2048, HD / 32, Cb, NSEQ, 1.f,
                         g_rowsum + bh * NSEQ + i0);
}

__global__ void __launch_bounds__(256) pv_hmma_kernel(float* __restrict__ out)
{
    int bg = blockIdx.y, b = bg >> 4, g = bg & 15;
    int i0 = blockIdx.x << 7;
    const float* Ap = g_E + (size_t)bg * NSEQ * NSEQ + (size_t)i0 * NSEQ;
    const float* Bp = g_vt + ((size_t)b * DMODEL + g * HD) * NSEQ;
    float* Cb = out + ((size_t)(b * NSEQ + i0)) * DMODEL + g * HD;
    hmma_core<64, false>(Ap, NSEQ, Bp, NSEQ, NSEQ / 32, Cb, DMODEL, 1.f, nullptr);
}

// ------------------- transpose v: [b][j][c] -> [b][c][j] --------------------
__global__ void __launch_bounds__(256) transpose_v_kernel()
{
    __shared__ float t[32][33];
    int j0 = blockIdx.x << 5, c0 = blockIdx.y << 5, b = blockIdx.z;
    int tx = threadIdx.x, ty = threadIdx.y;
#pragma unroll
    for (int i = 0; i < 4; i++)
        t[ty + i * 8][tx] =
            g_kv[((size_t)(b * NSEQ) + j0 + ty + i * 8) * 2048 + 1024 + c0 + tx];
    __syncthreads();
#pragma unroll
    for (int i = 0; i < 4; i++)
        g_vt[((size_t)b * DMODEL + c0 + ty + i * 8) * NSEQ + j0 + tx] =
            t[tx][ty + i * 8];
}

// ------ softmax-normalize + talking-heads mix + LayerNorm across heads -----
__global__ void __launch_bounds__(128) talkln_kernel(
    const float* __restrict__ Wtalk, const float* __restrict__ gamma,
    const float* __restrict__ beta)
{
    __shared__ float ws[256];
    __shared__ float rinv[16], gam[16], bet[16];
    const int tid = threadIdx.x;
    const int bi = blockIdx.y;
    const int b = bi >> 11, i = bi & 2047;
    const int j0 = (blockIdx.x << 9) + tid * 4;
    ws[tid]       = Wtalk[tid];
    ws[tid + 128] = Wtalk[tid + 128];
    if (tid < 16) {
        rinv[tid] = 1.0f / g_rowsum[(b * HN + tid) * NSEQ + i];
        gam[tid] = gamma[tid];
        bet[tid] = beta[tid];
    }
    __syncthreads();

    const size_t PL = (size_t)NSEQ * NSEQ;
    const size_t base0 = (size_t)(b * HN) * PL + (size_t)i * NSEQ + j0;

    u64 p2[16][2];
    u64 t2[16][2] = {};
#pragma unroll
    for (int h = 0; h < 16; h++) {
        float4 v = *(const float4*)&g_E[base0 + (size_t)h * PL];
        float s = rinv[h];
        v.x *= s; v.y *= s; v.z *= s; v.w *= s;
        *(float4*)&p2[h][0] = v;
    }
#pragma unroll
    for (int h = 0; h < 16; h++) {
#pragma unroll
        for (int g = 0; g < 16; g++) {
            u64 w2 = bcast2(ws[g * 16 + h]);
            fma2(t2[g][0], w2, p2[h][0]);
            fma2(t2[g][1], w2, p2[h][1]);
        }
    }
    float4 t[16];
#pragma unroll
    for (int g = 0; g < 16; g++) t[g] = *(const float4*)&t2[g][0];

    float4 mu = make_float4(0.f, 0.f, 0.f, 0.f);
#pragma unroll
    for (int g = 0; g < 16; g++) {
        mu.x += t[g].x; mu.y += t[g].y; mu.z += t[g].z; mu.w += t[g].w;
    }
    const float inv16 = 1.0f / 16.0f;
    mu.x *= inv16; mu.y *= inv16; mu.z *= inv16; mu.w *= inv16;
    float4 m2 = make_float4(0.f, 0.f, 0.f, 0.f);
#pragma unroll
    for (int g = 0; g < 16; g++) {
        float dx = t[g].x - mu.x, dy = t[g].y - mu.y;
        float dz = t[g].z - mu.z, dw = t[g].w - mu.w;
        m2.x = fmaf(dx, dx, m2.x); m2.y = fmaf(dy, dy, m2.y);
        m2.z = fmaf(dz, dz, m2.z); m2.w = fmaf(dw, dw, m2.w);
    }
    float4 rs;
    rs.x = rsqrtf(m2.x * inv16 + LN_EPS);
    rs.y = rsqrtf(m2.y * inv16 + LN_EPS);
    rs.z = rsqrtf(m2.z * inv16 + LN_EPS);
    rs.w = rsqrtf(m2.w * inv16 + LN_EPS);
#pragma unroll
    for (int g = 0; g < 16; g++) {
        float gg = gam[g], bb = bet[g];
        float4 o;
        o.x = fmaf((t[g].x - mu.x) * rs.x, gg, bb);
        o.y = fmaf((t[g].y - mu.y) * rs.y, gg, bb);
        o.z = fmaf((t[g].z - mu.z) * rs.z, gg, bb);
        o.w = fmaf((t[g].w - mu.w) * rs.w, gg, bb);
        *(float4*)&g_E[base0 + (size_t)g * PL] = o;
    }
}

__global__ void zero_rowsum_kernel()
{
    int i = blockIdx.x * 256 + threadIdx.x;
    if (i < NB * HN * NSEQ) g_rowsum[i] = 0.f;
}

// ---------------------------------------------------------------------------
extern "C" void kernel_launch(void* const* d_in, const int* in_sizes, int n_in,
                              void* d_out, int out_size)
{
    const float* x       = (const float*)d_in[0];
    const float* context = (const float*)d_in[1];
    const float* Wq      = (const float*)d_in[2];
    const float* Wkv     = (const float*)d_in[3];
    const float* Wtalk   = (const float*)d_in[4];
    const float* gamma   = (const float*)d_in[5];
    const float* beta    = (const float*)d_in[6];
    float* out = (float*)d_out;

    float *qp, *kvp;
    cudaGetSymbolAddress((void**)&qp, g_q);
    cudaGetSymbolAddress((void**)&kvp, g_kv);

    zero_rowsum_kernel<<<(NB * HN * NSEQ + 255) / 256, 256>>>();

    // q = x @ Wq^T (scaled), kv = context @ Wkv^T
    gemm_hmma_kernel<<<dim3(DMODEL / 128, (NB * NSEQ) / 128), 256>>>(
        x, Wq, qp, DMODEL, 0.125f);
    gemm_hmma_kernel<<<dim3(2048 / 128, (NB * NSEQ) / 128), 256>>>(
        context, Wkv, kvp, 2048, 1.0f);

    // v -> vt for the PV GEMM
    transpose_v_kernel<<<dim3(NSEQ / 32, DMODEL / 32, NB), dim3(32, 8)>>>();

    // exp(q k^T) per head + row sums
    scores_hmma_kernel<<<dim3(NSEQ / 128, NSEQ / 128, NB * HN), 256>>>();

    // softmax-normalize + talking heads + LN across heads (in place)
    talkln_kernel<<<dim3(4, NB * NSEQ), 128>>>(Wtalk, gamma, beta);

    // attn = aw @ v, written directly in final [b, n, h*d] layout
    pv_hmma_kernel<<<dim3(NSEQ / 128, NB * HN), 256>>>(out);
}

// round 6
// speedup vs baseline: 1.0739x; 1.0739x over previous
#include <cuda_runtime.h>
#include <cuda_fp16.h>
#include <cstdint>
#include <cstddef>

#define HN     16
#define DMODEL 1024
#define NSEQ   2048
#define NB     2
#define HD     64
#define LN_EPS 1e-5f

typedef unsigned long long u64;

// ---------------- scratch (device globals; no allocation allowed) ----------
__device__ float g_q [(size_t)NB * NSEQ * DMODEL];        // 16.8 MB
__device__ float g_kv[(size_t)NB * NSEQ * 2048];          // 33.5 MB (k | v)
__device__ float g_vt[(size_t)NB * DMODEL * NSEQ];        // 16.8 MB v transposed
__device__ float g_E [(size_t)NB * HN * NSEQ * NSEQ];     // 537 MB exp(scores) -> aw
__device__ float g_rowsum[NB * HN * NSEQ];

// -------------------- packed f32x2 helpers (talkln) ------------------------
__device__ __forceinline__ u64 bcast2(float x) {
    u64 r;
    unsigned u = __float_as_uint(x);
    asm("mov.b64 %0, {%1, %1};" : "=l"(r) : "r"(u));
    return r;
}
__device__ __forceinline__ void fma2(u64& d, u64 a, u64 b) {
    asm("fma.rn.f32x2 %0, %1, %2, %0;" : "+l"(d) : "l"(a), "l"(b));
}

// ---------------- fast exp on the FMA pipe (avoid MUFU.EX2) ----------------
__device__ __forceinline__ float fast_exp(float x) {
    float t = x * 1.4426950408889634f;
    float r = rintf(t);
    float f = t - r;
    float p =      1.5403530394e-4f;
    p = fmaf(p, f, 1.3333558146e-3f);
    p = fmaf(p, f, 9.6181291076e-3f);
    p = fmaf(p, f, 5.5504108665e-2f);
    p = fmaf(p, f, 2.4022650696e-1f);
    p = fmaf(p, f, 6.9314718056e-1f);
    p = fmaf(p, f, 1.0f);
    return p * __int_as_float(((int)r + 127) << 23);
}

// ------------------------- mma.sync fp16 wrapper ----------------------------
__device__ __forceinline__ void mma16816(
    float (&c)[4], const uint32_t (&a)[4], uint32_t b0, uint32_t b1)
{
    asm volatile(
        "mma.sync.aligned.m16n8k16.row.col.f32.f16.f16.f32 "
        "{%0,%1,%2,%3}, {%4,%5,%6,%7}, {%8,%9}, {%0,%1,%2,%3};"
        : "+f"(c[0]), "+f"(c[1]), "+f"(c[2]), "+f"(c[3])
        : "r"(a[0]), "r"(a[1]), "r"(a[2]), "r"(a[3]), "r"(b0), "r"(b1));
}
__device__ __forceinline__ uint32_t lds32(const uint16_t* p, int off) {
    return *(const uint32_t*)(p + off);
}

// Stage ROWS x 32 fp32 tile as fp16 (optionally hi/lo split), stride 36 elems.
template<int ROWS, int SPLIT>
__device__ __forceinline__ void stage_h(
    uint16_t* __restrict__ hi, uint16_t* __restrict__ lo,
    const float* __restrict__ src, size_t stride, int tid)
{
#pragma unroll
    for (int s = 0; s < ROWS / 32; s++) {
        int idx = s * 256 + tid;
        int row = idx >> 3;
        int cg  = idx & 7;
        float4 v = *(const float4*)(src + (size_t)row * stride + cg * 4);
        __half2 h01 = __floats2half2_rn(v.x, v.y);
        __half2 h23 = __floats2half2_rn(v.z, v.w);
        int off = row * 36 + cg * 4;
        *(uint2*)(hi + off) = make_uint2(*(uint32_t*)&h01, *(uint32_t*)&h23);
        if (SPLIT == 3) {
            float rx = v.x - __half2float(__low2half(h01));
            float ry = v.y - __half2float(__high2half(h01));
            float rz = v.z - __half2float(__low2half(h23));
            float rw = v.w - __half2float(__high2half(h23));
            __half2 l01 = __floats2half2_rn(rx, ry);
            __half2 l23 = __floats2half2_rn(rz, rw);
            *(uint2*)(lo + off) = make_uint2(*(uint32_t*)&l01, *(uint32_t*)&l23);
        }
    }
}

// ---- HMMA fp16 core: C[128 x NT] = A[128,K] @ B[NT,K]^T  (NT 64/128) ------
// 256 threads = 8 warps (4 x 2). Warp tile 32 x (NT/2). K-chunk 32.
// SPLIT=3: hi/lo split emulation (~2^-22 residual); SPLIT=1: plain fp16.
template<int NT, bool EXP_EPI, int SPLIT>
__device__ __forceinline__ void hmma_core(
    const float* __restrict__ A, size_t lda,
    const float* __restrict__ B, size_t ldb,
    int nk, float* __restrict__ C, size_t ldc,
    float alpha, float* __restrict__ rowsum)
{
    constexpr int NTILES = NT / 16;
    __shared__ __align__(16) uint16_t sAhi[128 * 36];
    __shared__ __align__(16) uint16_t sAlo[SPLIT == 3 ? 128 * 36 : 8];
    __shared__ __align__(16) uint16_t sBhi[NT * 36];
    __shared__ __align__(16) uint16_t sBlo[SPLIT == 3 ? NT * 36 : 8];

    const int tid  = threadIdx.x;
    const int wid  = tid >> 5;
    const int lane = tid & 31;
    const int wm = wid & 3, wn = wid >> 2;
    const int g = lane >> 2, t = lane & 3;

    float acc[2][NTILES][4];
#pragma unroll
    for (int mt = 0; mt < 2; mt++)
#pragma unroll
        for (int nt = 0; nt < NTILES; nt++)
#pragma unroll
            for (int q = 0; q < 4; q++) acc[mt][nt][q] = 0.f;

    for (int i = 0; i < nk; i++) {
        __syncthreads();
        stage_h<128, SPLIT>(sAhi, sAlo, A + (size_t)i * 32, lda, tid);
        stage_h<NT , SPLIT>(sBhi, sBlo, B + (size_t)i * 32, ldb, tid);
        __syncthreads();
#pragma unroll
        for (int ks = 0; ks < 2; ks++) {
            uint32_t ah[2][4], al[2][4];
#pragma unroll
            for (int mt = 0; mt < 2; mt++) {
                int r0 = (wm * 32 + mt * 16 + g) * 36 + ks * 16 + 2 * t;
                ah[mt][0] = lds32(sAhi, r0);
                ah[mt][1] = lds32(sAhi, r0 + 8 * 36);
                ah[mt][2] = lds32(sAhi, r0 + 8);
                ah[mt][3] = lds32(sAhi, r0 + 8 * 36 + 8);
                if (SPLIT == 3) {
                    al[mt][0] = lds32(sAlo, r0);
                    al[mt][1] = lds32(sAlo, r0 + 8 * 36);
                    al[mt][2] = lds32(sAlo, r0 + 8);
                    al[mt][3] = lds32(sAlo, r0 + 8 * 36 + 8);
                }
            }
#pragma unroll
            for (int nt = 0; nt < NTILES; nt++) {
                int c0 = (wn * (NT / 2) + nt * 8 + g) * 36 + ks * 16 + 2 * t;
                uint32_t bh0 = lds32(sBhi, c0), bh1 = lds32(sBhi, c0 + 8);
#pragma unroll
                for (int mt = 0; mt < 2; mt++)
                    mma16816(acc[mt][nt], ah[mt], bh0, bh1);
                if (SPLIT == 3) {
                    uint32_t bl0 = lds32(sBlo, c0), bl1 = lds32(sBlo, c0 + 8);
#pragma unroll
                    for (int mt = 0; mt < 2; mt++) {
                        mma16816(acc[mt][nt], ah[mt], bl0, bl1);
                        mma16816(acc[mt][nt], al[mt], bh0, bh1);
                    }
                }
            }
        }
    }

    // epilogue: thread holds rows {R, R+8}, cols ncol+2t(+1) per ntile
#pragma unroll
    for (int mt = 0; mt < 2; mt++) {
        int r0 = wm * 32 + mt * 16 + g;
        float rs0 = 0.f, rs1 = 0.f;
#pragma unroll
        for (int nt = 0; nt < NTILES; nt++) {
            int col = wn * (NT / 2) + nt * 8 + 2 * t;
            float2 lo_pair, hi_pair;
            if (EXP_EPI) {
                lo_pair.x = fast_exp(acc[mt][nt][0]);
                lo_pair.y = fast_exp(acc[mt][nt][1]);
                hi_pair.x = fast_exp(acc[mt][nt][2]);
                hi_pair.y = fast_exp(acc[mt][nt][3]);
                rs0 += lo_pair.x + lo_pair.y;
                rs1 += hi_pair.x + hi_pair.y;
            } else {
                lo_pair.x = acc[mt][nt][0] * alpha;
                lo_pair.y = acc[mt][nt][1] * alpha;
                hi_pair.x = acc[mt][nt][2] * alpha;
                hi_pair.y = acc[mt][nt][3] * alpha;
            }
            *(float2*)(C + (size_t)r0 * ldc + col)       = lo_pair;
            *(float2*)(C + (size_t)(r0 + 8) * ldc + col) = hi_pair;
        }
        if (EXP_EPI) {
            rs0 += __shfl_down_sync(0xffffffffu, rs0, 1, 4);
            rs0 += __shfl_down_sync(0xffffffffu, rs0, 2, 4);
            rs1 += __shfl_down_sync(0xffffffffu, rs1, 1, 4);
            rs1 += __shfl_down_sync(0xffffffffu, rs1, 2, 4);
            if (t == 0) {
                atomicAdd(&rowsum[r0], rs0);
                atomicAdd(&rowsum[r0 + 8], rs1);
            }
        }
    }
}

// ------------------------------- wrappers ----------------------------------
__global__ void __launch_bounds__(256) gemm_hmma_kernel(
    const float* __restrict__ A, const float* __restrict__ B,
    float* __restrict__ C, int N, float alpha)
{
    int m0 = blockIdx.y << 7, n0 = blockIdx.x << 7;
    hmma_core<128, false, 1>(A + (size_t)m0 * DMODEL, DMODEL,
                             B + (size_t)n0 * DMODEL, DMODEL, DMODEL / 32,
                             C + (size_t)m0 * N + n0, (size_t)N, alpha, nullptr);
}

__global__ void __launch_bounds__(256) scores_hmma_kernel()
{
    int bh = blockIdx.z, b = bh >> 4, h = bh & 15;
    int i0 = blockIdx.y << 7, j0 = blockIdx.x << 7;
    const float* Ap = g_q  + ((size_t)(b * NSEQ + i0)) * DMODEL + h * HD;
    const float* Bp = g_kv + ((size_t)(b * NSEQ + j0)) * 2048   + h * HD;
    float* Cb = g_E + (size_t)bh * NSEQ * NSEQ + (size_t)i0 * NSEQ + j0;
    hmma_core<128, true, 3>(Ap, DMODEL, Bp, 2048, HD / 32, Cb, NSEQ, 1.f,
                            g_rowsum + bh * NSEQ + i0);
}

__global__ void __launch_bounds__(256) pv_hmma_kernel(float* __restrict__ out)
{
    int bg = blockIdx.y, b = bg >> 4, g = bg & 15;
    int i0 = blockIdx.x << 7;
    const float* Ap = g_E + (size_t)bg * NSEQ * NSEQ + (size_t)i0 * NSEQ;
    const float* Bp = g_vt + ((size_t)b * DMODEL + g * HD) * NSEQ;
    float* Cb = out + ((size_t)(b * NSEQ + i0)) * DMODEL + g * HD;
    hmma_core<64, false, 1>(Ap, NSEQ, Bp, NSEQ, NSEQ / 32, Cb, DMODEL, 1.f,
                            nullptr);
}

// ------------------- transpose v: [b][j][c] -> [b][c][j] --------------------
__global__ void __launch_bounds__(256) transpose_v_kernel()
{
    __shared__ float t[32][33];
    int j0 = blockIdx.x << 5, c0 = blockIdx.y << 5, b = blockIdx.z;
    int tx = threadIdx.x, ty = threadIdx.y;
#pragma unroll
    for (int i = 0; i < 4; i++)
        t[ty + i * 8][tx] =
            g_kv[((size_t)(b * NSEQ) + j0 + ty + i * 8) * 2048 + 1024 + c0 + tx];
    __syncthreads();
#pragma unroll
    for (int i = 0; i < 4; i++)
        g_vt[((size_t)b * DMODEL + c0 + ty + i * 8) * NSEQ + j0 + tx] =
            t[tx][ty + i * 8];
}

// ------ softmax-normalize + talking-heads mix + LayerNorm across heads -----
__global__ void __launch_bounds__(128) talkln_kernel(
    const float* __restrict__ Wtalk, const float* __restrict__ gamma,
    const float* __restrict__ beta)
{
    __shared__ float ws[256];
    __shared__ float rinv[16], gam[16], bet[16];
    const int tid = threadIdx.x;
    const int bi = blockIdx.y;
    const int b = bi >> 11, i = bi & 2047;
    const int j0 = (blockIdx.x << 9) + tid * 4;
    ws[tid]       = Wtalk[tid];
    ws[tid + 128] = Wtalk[tid + 128];
    if (tid < 16) {
        rinv[tid] = 1.0f / g_rowsum[(b * HN + tid) * NSEQ + i];
        gam[tid] = gamma[tid];
        bet[tid] = beta[tid];
    }
    __syncthreads();

    const size_t PL = (size_t)NSEQ * NSEQ;
    const size_t base0 = (size_t)(b * HN) * PL + (size_t)i * NSEQ + j0;

    u64 p2[16][2];
    u64 t2[16][2] = {};
#pragma unroll
    for (int h = 0; h < 16; h++) {
        float4 v = *(const float4*)&g_E[base0 + (size_t)h * PL];
        float s = rinv[h];
        v.x *= s; v.y *= s; v.z *= s; v.w *= s;
        *(float4*)&p2[h][0] = v;
    }
#pragma unroll
    for (int h = 0; h < 16; h++) {
#pragma unroll
        for (int g = 0; g < 16; g++) {
            u64 w2 = bcast2(ws[g * 16 + h]);
            fma2(t2[g][0], w2, p2[h][0]);
            fma2(t2[g][1], w2, p2[h][1]);
        }
    }
    float4 t[16];
#pragma unroll
    for (int g = 0; g < 16; g++) t[g] = *(const float4*)&t2[g][0];

    float4 mu = make_float4(0.f, 0.f, 0.f, 0.f);
#pragma unroll
    for (int g = 0; g < 16; g++) {
        mu.x += t[g].x; mu.y += t[g].y; mu.z += t[g].z; mu.w += t[g].w;
    }
    const float inv16 = 1.0f / 16.0f;
    mu.x *= inv16; mu.y *= inv16; mu.z *= inv16; mu.w *= inv16;
    float4 m2 = make_float4(0.f, 0.f, 0.f, 0.f);
#pragma unroll
    for (int g = 0; g < 16; g++) {
        float dx = t[g].x - mu.x, dy = t[g].y - mu.y;
        float dz = t[g].z - mu.z, dw = t[g].w - mu.w;
        m2.x = fmaf(dx, dx, m2.x); m2.y = fmaf(dy, dy, m2.y);
        m2.z = fmaf(dz, dz, m2.z); m2.w = fmaf(dw, dw, m2.w);
    }
    float4 rs;
    rs.x = rsqrtf(m2.x * inv16 + LN_EPS);
    rs.y = rsqrtf(m2.y * inv16 + LN_EPS);
    rs.z = rsqrtf(m2.z * inv16 + LN_EPS);
    rs.w = rsqrtf(m2.w * inv16 + LN_EPS);
#pragma unroll
    for (int g = 0; g < 16; g++) {
        float gg = gam[g], bb = bet[g];
        float4 o;
        o.x = fmaf((t[g].x - mu.x) * rs.x, gg, bb);
        o.y = fmaf((t[g].y - mu.y) * rs.y, gg, bb);
        o.z = fmaf((t[g].z - mu.z) * rs.z, gg, bb);
        o.w = fmaf((t[g].w - mu.w) * rs.w, gg, bb);
        *(float4*)&g_E[base0 + (size_t)g * PL] = o;
    }
}

__global__ void zero_rowsum_kernel()
{
    int i = blockIdx.x * 256 + threadIdx.x;
    if (i < NB * HN * NSEQ) g_rowsum[i] = 0.f;
}

// ---------------------------------------------------------------------------
extern "C" void kernel_launch(void* const* d_in, const int* in_sizes, int n_in,
                              void* d_out, int out_size)
{
    const float* x       = (const float*)d_in[0];
    const float* context = (const float*)d_in[1];
    const float* Wq      = (const float*)d_in[2];
    const float* Wkv     = (const float*)d_in[3];
    const float* Wtalk   = (const float*)d_in[4];
    const float* gamma   = (const float*)d_in[5];
    const float* beta    = (const float*)d_in[6];
    float* out = (float*)d_out;

    float *qp, *kvp;
    cudaGetSymbolAddress((void**)&qp, g_q);
    cudaGetSymbolAddress((void**)&kvp, g_kv);

    zero_rowsum_kernel<<<(NB * HN * NSEQ + 255) / 256, 256>>>();

    // q = x @ Wq^T (scaled), kv = context @ Wkv^T   (single fp16)
    gemm_hmma_kernel<<<dim3(DMODEL / 128, (NB * NSEQ) / 128), 256>>>(
        x, Wq, qp, DMODEL, 0.125f);
    gemm_hmma_kernel<<<dim3(2048 / 128, (NB * NSEQ) / 128), 256>>>(
        context, Wkv, kvp, 2048, 1.0f);

    // v -> vt for the PV GEMM
    transpose_v_kernel<<<dim3(NSEQ / 32, DMODEL / 32, NB), dim3(32, 8)>>>();

    // exp(q k^T) per head + row sums   (fp16 split-3, exp-protected)
    scores_hmma_kernel<<<dim3(NSEQ / 128, NSEQ / 128, NB * HN), 256>>>();

    // softmax-normalize + talking heads + LN across heads (in place)
    talkln_kernel<<<dim3(4, NB * NSEQ), 128>>>(Wtalk, gamma, beta);

    // attn = aw @ v   (single fp16), final [b, n, h*d] layout
    pv_hmma_kernel<<<dim3(NSEQ / 128, NB * HN), 256>>>(out);
}

// round 7
// speedup vs baseline: 1.3040x; 1.2143x over previous
#include <cuda_runtime.h>
#include <cuda_fp16.h>
#include <cstdint>
#include <cstddef>

#define HN     16
#define DMODEL 1024
#define NSEQ   2048
#define NB     2
#define HD     64
#define LN_EPS 1e-5f
#define SSTR   40          // smem stride in halfs (80B, 16B-aligned rows)

typedef unsigned long long u64;

// ---------------- scratch (device globals; no allocation allowed) ----------
__device__ float g_q [(size_t)NB * NSEQ * DMODEL];
__device__ float g_kv[(size_t)NB * NSEQ * 2048];
__device__ float g_vt[(size_t)NB * DMODEL * NSEQ];
__device__ float g_E [(size_t)NB * HN * NSEQ * NSEQ];
__device__ float g_rowsum[NB * HN * NSEQ];

// -------------------- packed f32x2 helpers (talkln) ------------------------
__device__ __forceinline__ u64 bcast2(float x) {
    u64 r;
    unsigned u = __float_as_uint(x);
    asm("mov.b64 %0, {%1, %1};" : "=l"(r) : "r"(u));
    return r;
}
__device__ __forceinline__ void fma2(u64& d, u64 a, u64 b) {
    asm("fma.rn.f32x2 %0, %1, %2, %0;" : "+l"(d) : "l"(a), "l"(b));
}

// ---------------- fast exp on the FMA pipe (avoid MUFU.EX2) ----------------
__device__ __forceinline__ float fast_exp(float x) {
    float t = x * 1.4426950408889634f;
    float r = rintf(t);
    float f = t - r;
    float p =      1.5403530394e-4f;
    p = fmaf(p, f, 1.3333558146e-3f);
    p = fmaf(p, f, 9.6181291076e-3f);
    p = fmaf(p, f, 5.5504108665e-2f);
    p = fmaf(p, f, 2.4022650696e-1f);
    p = fmaf(p, f, 6.9314718056e-1f);
    p = fmaf(p, f, 1.0f);
    return p * __int_as_float(((int)r + 127) << 23);
}

// ------------------------- mma.sync / ldmatrix ------------------------------
__device__ __forceinline__ void mma16816(
    float (&c)[4], const uint32_t (&a)[4], uint32_t b0, uint32_t b1)
{
    asm volatile(
        "mma.sync.aligned.m16n8k16.row.col.f32.f16.f16.f32 "
        "{%0,%1,%2,%3}, {%4,%5,%6,%7}, {%8,%9}, {%0,%1,%2,%3};"
        : "+f"(c[0]), "+f"(c[1]), "+f"(c[2]), "+f"(c[3])
        : "r"(a[0]), "r"(a[1]), "r"(a[2]), "r"(a[3]), "r"(b0), "r"(b1));
}
__device__ __forceinline__ void ldsm_x4(uint32_t (&r)[4], uint32_t addr) {
    asm volatile("ldmatrix.sync.aligned.m8n8.x4.shared.b16 {%0,%1,%2,%3}, [%4];"
        : "=r"(r[0]), "=r"(r[1]), "=r"(r[2]), "=r"(r[3]) : "r"(addr));
}

// Stage ROWS x 32 fp32 tile as fp16 (optionally hi/lo split), stride SSTR.
template<int ROWS, int SPLIT>
__device__ __forceinline__ void stage_h(
    uint16_t* __restrict__ hi, uint16_t* __restrict__ lo,
    const float* __restrict__ src, size_t stride, int tid)
{
#pragma unroll
    for (int s = 0; s < ROWS / 32; s++) {
        int idx = s * 256 + tid;
        int row = idx >> 3;
        int cg  = idx & 7;
        float4 v = *(const float4*)(src + (size_t)row * stride + cg * 4);
        __half2 h01 = __floats2half2_rn(v.x, v.y);
        __half2 h23 = __floats2half2_rn(v.z, v.w);
        int off = row * SSTR + cg * 4;
        *(uint2*)(hi + off) = make_uint2(*(uint32_t*)&h01, *(uint32_t*)&h23);
        if (SPLIT == 3) {
            float rx = v.x - __half2float(__low2half(h01));
            float ry = v.y - __half2float(__high2half(h01));
            float rz = v.z - __half2float(__low2half(h23));
            float rw = v.w - __half2float(__high2half(h23));
            __half2 l01 = __floats2half2_rn(rx, ry);
            __half2 l23 = __floats2half2_rn(rz, rw);
            *(uint2*)(lo + off) = make_uint2(*(uint32_t*)&l01, *(uint32_t*)&l23);
        }
    }
}

// ---- HMMA fp16 core: C[128 x NT] = A[128,K] @ B[NT,K]^T  (NT 64/128) ------
// 256 threads = 8 warps (4 x 2). Warp tile 32 x (NT/2). K-chunk 32.
// Fragments via ldmatrix.x4 (16B-aligned rows, conflict-free at stride 80B).
template<int NT, bool EXP_EPI, int SPLIT>
__device__ __forceinline__ void hmma_core(
    const float* __restrict__ A, size_t lda,
    const float* __restrict__ B, size_t ldb,
    int nk, float* __restrict__ C, size_t ldc,
    float alpha, float* __restrict__ rowsum)
{
    constexpr int NTILES = NT / 16;
    constexpr int NPAIRS = NTILES / 2;
    __shared__ __align__(16) uint16_t sAhi[128 * SSTR];
    __shared__ __align__(16) uint16_t sAlo[SPLIT == 3 ? 128 * SSTR : 8];
    __shared__ __align__(16) uint16_t sBhi[NT * SSTR];
    __shared__ __align__(16) uint16_t sBlo[SPLIT == 3 ? NT * SSTR : 8];

    const int tid  = threadIdx.x;
    const int wid  = tid >> 5;
    const int lane = tid & 31;
    const int wm = wid & 3, wn = wid >> 2;
    const int g = lane >> 2, t = lane & 3;

    // per-lane ldmatrix byte offsets (within a tile)
    const uint32_t aoff = (uint32_t)((lane & 15) * (SSTR * 2) + (lane >> 4) * 16);
    const uint32_t boff = (uint32_t)(((lane & 7) + ((lane >> 4) * 8)) * (SSTR * 2)
                                     + ((lane >> 3) & 1) * 16);
    const uint32_t aHiB = (uint32_t)__cvta_generic_to_shared(sAhi)
                          + aoff + (uint32_t)(wm * 32 * SSTR * 2);
    const uint32_t aLoB = (uint32_t)__cvta_generic_to_shared(sAlo)
                          + aoff + (uint32_t)(wm * 32 * SSTR * 2);
    const uint32_t bHiB = (uint32_t)__cvta_generic_to_shared(sBhi)
                          + boff + (uint32_t)(wn * (NT / 2) * SSTR * 2);
    const uint32_t bLoB = (uint32_t)__cvta_generic_to_shared(sBlo)
                          + boff + (uint32_t)(wn * (NT / 2) * SSTR * 2);

    float acc[2][NTILES][4];
#pragma unroll
    for (int mt = 0; mt < 2; mt++)
#pragma unroll
        for (int nt = 0; nt < NTILES; nt++)
#pragma unroll
            for (int q = 0; q < 4; q++) acc[mt][nt][q] = 0.f;

    for (int i = 0; i < nk; i++) {
        __syncthreads();
        stage_h<128, SPLIT>(sAhi, sAlo, A + (size_t)i * 32, lda, tid);
        stage_h<NT , SPLIT>(sBhi, sBlo, B + (size_t)i * 32, ldb, tid);
        __syncthreads();
#pragma unroll
        for (int ks = 0; ks < 2; ks++) {
            uint32_t ah[2][4], al[2][4];
            ldsm_x4(ah[0], aHiB + ks * 32);
            ldsm_x4(ah[1], aHiB + 16 * SSTR * 2 + ks * 32);
            if (SPLIT == 3) {
                ldsm_x4(al[0], aLoB + ks * 32);
                ldsm_x4(al[1], aLoB + 16 * SSTR * 2 + ks * 32);
            }
#pragma unroll
            for (int np = 0; np < NPAIRS; np++) {
                uint32_t bh[4];
                ldsm_x4(bh, bHiB + np * 16 * SSTR * 2 + ks * 32);
                mma16816(acc[0][2*np],   ah[0], bh[0], bh[1]);
                mma16816(acc[1][2*np],   ah[1], bh[0], bh[1]);
                mma16816(acc[0][2*np+1], ah[0], bh[2], bh[3]);
                mma16816(acc[1][2*np+1], ah[1], bh[2], bh[3]);
                if (SPLIT == 3) {
                    uint32_t bl[4];
                    ldsm_x4(bl, bLoB + np * 16 * SSTR * 2 + ks * 32);
                    mma16816(acc[0][2*np],   ah[0], bl[0], bl[1]);
                    mma16816(acc[1][2*np],   ah[1], bl[0], bl[1]);
                    mma16816(acc[0][2*np+1], ah[0], bl[2], bl[3]);
                    mma16816(acc[1][2*np+1], ah[1], bl[2], bl[3]);
                    mma16816(acc[0][2*np],   al[0], bh[0], bh[1]);
                    mma16816(acc[1][2*np],   al[1], bh[0], bh[1]);
                    mma16816(acc[0][2*np+1], al[0], bh[2], bh[3]);
                    mma16816(acc[1][2*np+1], al[1], bh[2], bh[3]);
                }
            }
        }
    }

    // epilogue: thread holds rows {R, R+8}, cols ncol+2t(+1) per ntile
#pragma unroll
    for (int mt = 0; mt < 2; mt++) {
        int r0 = wm * 32 + mt * 16 + g;
        float rs0 = 0.f, rs1 = 0.f;
#pragma unroll
        for (int nt = 0; nt < NTILES; nt++) {
            int col = wn * (NT / 2) + nt * 8 + 2 * t;
            float2 lo_pair, hi_pair;
            if (EXP_EPI) {
                lo_pair.x = fast_exp(acc[mt][nt][0]);
                lo_pair.y = fast_exp(acc[mt][nt][1]);
                hi_pair.x = fast_exp(acc[mt][nt][2]);
                hi_pair.y = fast_exp(acc[mt][nt][3]);
                rs0 += lo_pair.x + lo_pair.y;
                rs1 += hi_pair.x + hi_pair.y;
            } else {
                lo_pair.x = acc[mt][nt][0] * alpha;
                lo_pair.y = acc[mt][nt][1] * alpha;
                hi_pair.x = acc[mt][nt][2] * alpha;
                hi_pair.y = acc[mt][nt][3] * alpha;
            }
            *(float2*)(C + (size_t)r0 * ldc + col)       = lo_pair;
            *(float2*)(C + (size_t)(r0 + 8) * ldc + col) = hi_pair;
        }
        if (EXP_EPI) {
            rs0 += __shfl_down_sync(0xffffffffu, rs0, 1, 4);
            rs0 += __shfl_down_sync(0xffffffffu, rs0, 2, 4);
            rs1 += __shfl_down_sync(0xffffffffu, rs1, 1, 4);
            rs1 += __shfl_down_sync(0xffffffffu, rs1, 2, 4);
            if (t == 0) {
                atomicAdd(&rowsum[r0], rs0);
                atomicAdd(&rowsum[r0 + 8], rs1);
            }
        }
    }
}

// ------------------------------- wrappers ----------------------------------
__global__ void __launch_bounds__(256, 2) gemm_hmma_kernel(
    const float* __restrict__ A, const float* __restrict__ B,
    float* __restrict__ C, int N, float alpha)
{
    int m0 = blockIdx.y << 7, n0 = blockIdx.x << 7;
    hmma_core<128, false, 1>(A + (size_t)m0 * DMODEL, DMODEL,
                             B + (size_t)n0 * DMODEL, DMODEL, DMODEL / 32,
                             C + (size_t)m0 * N + n0, (size_t)N, alpha, nullptr);
}

__global__ void __launch_bounds__(256) scores_hmma_kernel()
{
    int bh = blockIdx.z, b = bh >> 4, h = bh & 15;
    int i0 = blockIdx.y << 7, j0 = blockIdx.x << 7;
    const float* Ap = g_q  + ((size_t)(b * NSEQ + i0)) * DMODEL + h * HD;
    const float* Bp = g_kv + ((size_t)(b * NSEQ + j0)) * 2048   + h * HD;
    float* Cb = g_E + (size_t)bh * NSEQ * NSEQ + (size_t)i0 * NSEQ + j0;
    hmma_core<128, true, 3>(Ap, DMODEL, Bp, 2048, HD / 32, Cb, NSEQ, 1.f,
                            g_rowsum + bh * NSEQ + i0);
}

__global__ void __launch_bounds__(256, 2) pv_hmma_kernel(float* __restrict__ out)
{
    int bg = blockIdx.y, b = bg >> 4, g = bg & 15;
    int i0 = blockIdx.x << 7;
    const float* Ap = g_E + (size_t)bg * NSEQ * NSEQ + (size_t)i0 * NSEQ;
    const float* Bp = g_vt + ((size_t)b * DMODEL + g * HD) * NSEQ;
    float* Cb = out + ((size_t)(b * NSEQ + i0)) * DMODEL + g * HD;
    hmma_core<64, false, 1>(Ap, NSEQ, Bp, NSEQ, NSEQ / 32, Cb, DMODEL, 1.f,
                            nullptr);
}

// ------------------- transpose v: [b][j][c] -> [b][c][j] --------------------
__global__ void __launch_bounds__(256) transpose_v_kernel()
{
    __shared__ float t[32][33];
    int j0 = blockIdx.x << 5, c0 = blockIdx.y << 5, b = blockIdx.z;
    int tx = threadIdx.x, ty = threadIdx.y;
#pragma unroll
    for (int i = 0; i < 4; i++)
        t[ty + i * 8][tx] =
            g_kv[((size_t)(b * NSEQ) + j0 + ty + i * 8) * 2048 + 1024 + c0 + tx];
    __syncthreads();
#pragma unroll
    for (int i = 0; i < 4; i++)
        g_vt[((size_t)b * DMODEL + c0 + ty + i * 8) * NSEQ + j0 + tx] =
            t[tx][ty + i * 8];
}

// ------ softmax-normalize + talking-heads mix + LayerNorm across heads -----
__global__ void __launch_bounds__(128) talkln_kernel(
    const float* __restrict__ Wtalk, const float* __restrict__ gamma,
    const float* __restrict__ beta)
{
    __shared__ float ws[256];
    __shared__ float rinv[16], gam[16], bet[16];
    const int tid = threadIdx.x;
    const int bi = blockIdx.y;
    const int b = bi >> 11, i = bi & 2047;
    const int j0 = (blockIdx.x << 9) + tid * 4;
    ws[tid]       = Wtalk[tid];
    ws[tid + 128] = Wtalk[tid + 128];
    if (tid < 16) {
        rinv[tid] = 1.0f / g_rowsum[(b * HN + tid) * NSEQ + i];
        gam[tid] = gamma[tid];
        bet[tid] = beta[tid];
    }
    __syncthreads();

    const size_t PL = (size_t)NSEQ * NSEQ;
    const size_t base0 = (size_t)(b * HN) * PL + (size_t)i * NSEQ + j0;

    u64 p2[16][2];
    u64 t2[16][2] = {};
#pragma unroll
    for (int h = 0; h < 16; h++) {
        float4 v = *(const float4*)&g_E[base0 + (size_t)h * PL];
        float s = rinv[h];
        v.x *= s; v.y *= s; v.z *= s; v.w *= s;
        *(float4*)&p2[h][0] = v;
    }
#pragma unroll
    for (int h = 0; h < 16; h++) {
#pragma unroll
        for (int g = 0; g < 16; g++) {
            u64 w2 = bcast2(ws[g * 16 + h]);
            fma2(t2[g][0], w2, p2[h][0]);
            fma2(t2[g][1], w2, p2[h][1]);
        }
    }
    float4 t[16];
#pragma unroll
    for (int g = 0; g < 16; g++) t[g] = *(const float4*)&t2[g][0];

    float4 mu = make_float4(0.f, 0.f, 0.f, 0.f);
#pragma unroll
    for (int g = 0; g < 16; g++) {
        mu.x += t[g].x; mu.y += t[g].y; mu.z += t[g].z; mu.w += t[g].w;
    }
    const float inv16 = 1.0f / 16.0f;
    mu.x *= inv16; mu.y *= inv16; mu.z *= inv16; mu.w *= inv16;
    float4 m2 = make_float4(0.f, 0.f, 0.f, 0.f);
#pragma unroll
    for (int g = 0; g < 16; g++) {
        float dx = t[g].x - mu.x, dy = t[g].y - mu.y;
        float dz = t[g].z - mu.z, dw = t[g].w - mu.w;
        m2.x = fmaf(dx, dx, m2.x); m2.y = fmaf(dy, dy, m2.y);
        m2.z = fmaf(dz, dz, m2.z); m2.w = fmaf(dw, dw, m2.w);
    }
    float4 rs;
    rs.x = rsqrtf(m2.x * inv16 + LN_EPS);
    rs.y = rsqrtf(m2.y * inv16 + LN_EPS);
    rs.z = rsqrtf(m2.z * inv16 + LN_EPS);
    rs.w = rsqrtf(m2.w * inv16 + LN_EPS);
#pragma unroll
    for (int g = 0; g < 16; g++) {
        float gg = gam[g], bb = bet[g];
        float4 o;
        o.x = fmaf((t[g].x - mu.x) * rs.x, gg, bb);
        o.y = fmaf((t[g].y - mu.y) * rs.y, gg, bb);
        o.z = fmaf((t[g].z - mu.z) * rs.z, gg, bb);
        o.w = fmaf((t[g].w - mu.w) * rs.w, gg, bb);
        *(float4*)&g_E[base0 + (size_t)g * PL] = o;
    }
}

__global__ void zero_rowsum_kernel()
{
    int i = blockIdx.x * 256 + threadIdx.x;
    if (i < NB * HN * NSEQ) g_rowsum[i] = 0.f;
}

// ---------------------------------------------------------------------------
extern "C" void kernel_launch(void* const* d_in, const int* in_sizes, int n_in,
                              void* d_out, int out_size)
{
    const float* x       = (const float*)d_in[0];
    const float* context = (const float*)d_in[1];
    const float* Wq      = (const float*)d_in[2];
    const float* Wkv     = (const float*)d_in[3];
    const float* Wtalk   = (const float*)d_in[4];
    const float* gamma   = (const float*)d_in[5];
    const float* beta    = (const float*)d_in[6];
    float* out = (float*)d_out;

    float *qp, *kvp;
    cudaGetSymbolAddress((void**)&qp, g_q);
    cudaGetSymbolAddress((void**)&kvp, g_kv);

    zero_rowsum_kernel<<<(NB * HN * NSEQ + 255) / 256, 256>>>();

    // q = x @ Wq^T (scaled), kv = context @ Wkv^T   (single fp16)
    gemm_hmma_kernel<<<dim3(DMODEL / 128, (NB * NSEQ) / 128), 256>>>(
        x, Wq, qp, DMODEL, 0.125f);
    gemm_hmma_kernel<<<dim3(2048 / 128, (NB * NSEQ) / 128), 256>>>(
        context, Wkv, kvp, 2048, 1.0f);

    // v -> vt for the PV GEMM
    transpose_v_kernel<<<dim3(NSEQ / 32, DMODEL / 32, NB), dim3(32, 8)>>>();

    // exp(q k^T) per head + row sums   (fp16 split-3, exp-protected)
    scores_hmma_kernel<<<dim3(NSEQ / 128, NSEQ / 128, NB * HN), 256>>>();

    // softmax-normalize + talking heads + LN across heads (in place)
    talkln_kernel<<<dim3(4, NB * NSEQ), 128>>>(Wtalk, gamma, beta);

    // attn = aw @ v   (single fp16), final [b, n, h*d] layout
    pv_hmma_kernel<<<dim3(NSEQ / 128, NB * HN), 256>>>(out);
}

// round 8
// speedup vs baseline: 1.5162x; 1.1627x over previous
#include <cuda_runtime.h>
#include <cuda_fp16.h>
#include <cstdint>
#include <cstddef>

#define HN     16
#define DMODEL 1024
#define NSEQ   2048
#define NB     2
#define HD     64
#define LN_EPS 1e-5f
#define SSTR   40          // smem stride (halfs) for k=32 tiles
#define FSTR   72          // smem stride (halfs) for k=64 tiles (fused kernel)
#define ITILE  16          // fused kernel i-rows per block
#define JCH    64          // fused kernel j-chunk

typedef unsigned long long u64;

// ---------------- scratch (device globals; no allocation allowed) ----------
__device__ float  g_q [(size_t)NB * NSEQ * DMODEL];
__device__ float  g_kv[(size_t)NB * NSEQ * 2048];
__device__ __half g_vth[(size_t)NB * DMODEL * NSEQ];     // v transposed, fp16
__device__ float  g_E [(size_t)NB * HN * NSEQ * NSEQ];   // exp(scores)
__device__ float  g_rowsum[NB * HN * NSEQ];

// ---------------- fast exp on the FMA pipe (avoid MUFU.EX2) ----------------
__device__ __forceinline__ float fast_exp(float x) {
    float t = x * 1.4426950408889634f;
    float r = rintf(t);
    float f = t - r;
    float p =      1.5403530394e-4f;
    p = fmaf(p, f, 1.3333558146e-3f);
    p = fmaf(p, f, 9.6181291076e-3f);
    p = fmaf(p, f, 5.5504108665e-2f);
    p = fmaf(p, f, 2.4022650696e-1f);
    p = fmaf(p, f, 6.9314718056e-1f);
    p = fmaf(p, f, 1.0f);
    return p * __int_as_float(((int)r + 127) << 23);
}

// ------------------------- mma.sync / ldmatrix ------------------------------
__device__ __forceinline__ void mma16816(
    float (&c)[4], const uint32_t (&a)[4], uint32_t b0, uint32_t b1)
{
    asm volatile(
        "mma.sync.aligned.m16n8k16.row.col.f32.f16.f16.f32 "
        "{%0,%1,%2,%3}, {%4,%5,%6,%7}, {%8,%9}, {%0,%1,%2,%3};"
        : "+f"(c[0]), "+f"(c[1]), "+f"(c[2]), "+f"(c[3])
        : "r"(a[0]), "r"(a[1]), "r"(a[2]), "r"(a[3]), "r"(b0), "r"(b1));
}
__device__ __forceinline__ void ldsm_x4(uint32_t (&r)[4], uint32_t addr) {
    asm volatile("ldmatrix.sync.aligned.m8n8.x4.shared.b16 {%0,%1,%2,%3}, [%4];"
        : "=r"(r[0]), "=r"(r[1]), "=r"(r[2]), "=r"(r[3]) : "r"(addr));
}

// Stage ROWS x 32 fp32 tile as fp16 (optionally hi/lo split), stride SSTR.
template<int ROWS, int SPLIT>
__device__ __forceinline__ void stage_h(
    uint16_t* __restrict__ hi, uint16_t* __restrict__ lo,
    const float* __restrict__ src, size_t stride, int tid)
{
#pragma unroll
    for (int s = 0; s < ROWS / 32; s++) {
        int idx = s * 256 + tid;
        int row = idx >> 3;
        int cg  = idx & 7;
        float4 v = *(const float4*)(src + (size_t)row * stride + cg * 4);
        __half2 h01 = __floats2half2_rn(v.x, v.y);
        __half2 h23 = __floats2half2_rn(v.z, v.w);
        int off = row * SSTR + cg * 4;
        *(uint2*)(hi + off) = make_uint2(*(uint32_t*)&h01, *(uint32_t*)&h23);
        if (SPLIT == 3) {
            float rx = v.x - __half2float(__low2half(h01));
            float ry = v.y - __half2float(__high2half(h01));
            float rz = v.z - __half2float(__low2half(h23));
            float rw = v.w - __half2float(__high2half(h23));
            __half2 l01 = __floats2half2_rn(rx, ry);
            __half2 l23 = __floats2half2_rn(rz, rw);
            *(uint2*)(lo + off) = make_uint2(*(uint32_t*)&l01, *(uint32_t*)&l23);
        }
    }
}

// ---- HMMA fp16 core: C[128 x NT] = A[128,K] @ B[NT,K]^T -------------------
template<int NT, bool EXP_EPI, int SPLIT>
__device__ __forceinline__ void hmma_core(
    const float* __restrict__ A, size_t lda,
    const float* __restrict__ B, size_t ldb,
    int nk, float* __restrict__ C, size_t ldc,
    float alpha, float* __restrict__ rowsum)
{
    constexpr int NTILES = NT / 16;
    constexpr int NPAIRS = NTILES / 2;
    __shared__ __align__(16) uint16_t sAhi[128 * SSTR];
    __shared__ __align__(16) uint16_t sAlo[SPLIT == 3 ? 128 * SSTR : 8];
    __shared__ __align__(16) uint16_t sBhi[NT * SSTR];
    __shared__ __align__(16) uint16_t sBlo[SPLIT == 3 ? NT * SSTR : 8];

    const int tid  = threadIdx.x;
    const int wid  = tid >> 5;
    const int lane = tid & 31;
    const int wm = wid & 3, wn = wid >> 2;
    const int g = lane >> 2, t = lane & 3;

    const uint32_t aoff = (uint32_t)((lane & 15) * (SSTR * 2) + (lane >> 4) * 16);
    const uint32_t boff = (uint32_t)(((lane & 7) + ((lane >> 4) * 8)) * (SSTR * 2)
                                     + ((lane >> 3) & 1) * 16);
    const uint32_t aHiB = (uint32_t)__cvta_generic_to_shared(sAhi)
                          + aoff + (uint32_t)(wm * 32 * SSTR * 2);
    const uint32_t aLoB = (uint32_t)__cvta_generic_to_shared(sAlo)
                          + aoff + (uint32_t)(wm * 32 * SSTR * 2);
    const uint32_t bHiB = (uint32_t)__cvta_generic_to_shared(sBhi)
                          + boff + (uint32_t)(wn * (NT / 2) * SSTR * 2);
    const uint32_t bLoB = (uint32_t)__cvta_generic_to_shared(sBlo)
                          + boff + (uint32_t)(wn * (NT / 2) * SSTR * 2);

    float acc[2][NTILES][4];
#pragma unroll
    for (int mt = 0; mt < 2; mt++)
#pragma unroll
        for (int nt = 0; nt < NTILES; nt++)
#pragma unroll
            for (int q = 0; q < 4; q++) acc[mt][nt][q] = 0.f;

    for (int i = 0; i < nk; i++) {
        __syncthreads();
        stage_h<128, SPLIT>(sAhi, sAlo, A + (size_t)i * 32, lda, tid);
        stage_h<NT , SPLIT>(sBhi, sBlo, B + (size_t)i * 32, ldb, tid);
        __syncthreads();
#pragma unroll
        for (int ks = 0; ks < 2; ks++) {
            uint32_t ah[2][4], al[2][4];
            ldsm_x4(ah[0], aHiB + ks * 32);
            ldsm_x4(ah[1], aHiB + 16 * SSTR * 2 + ks * 32);
            if (SPLIT == 3) {
                ldsm_x4(al[0], aLoB + ks * 32);
                ldsm_x4(al[1], aLoB + 16 * SSTR * 2 + ks * 32);
            }
#pragma unroll
            for (int np = 0; np < NPAIRS; np++) {
                uint32_t bh[4];
                ldsm_x4(bh, bHiB + np * 16 * SSTR * 2 + ks * 32);
                mma16816(acc[0][2*np],   ah[0], bh[0], bh[1]);
                mma16816(acc[1][2*np],   ah[1], bh[0], bh[1]);
                mma16816(acc[0][2*np+1], ah[0], bh[2], bh[3]);
                mma16816(acc[1][2*np+1], ah[1], bh[2], bh[3]);
                if (SPLIT == 3) {
                    uint32_t bl[4];
                    ldsm_x4(bl, bLoB + np * 16 * SSTR * 2 + ks * 32);
                    mma16816(acc[0][2*np],   ah[0], bl[0], bl[1]);
                    mma16816(acc[1][2*np],   ah[1], bl[0], bl[1]);
                    mma16816(acc[0][2*np+1], ah[0], bl[2], bl[3]);
                    mma16816(acc[1][2*np+1], ah[1], bl[2], bl[3]);
                    mma16816(acc[0][2*np],   al[0], bh[0], bh[1]);
                    mma16816(acc[1][2*np],   al[1], bh[0], bh[1]);
                    mma16816(acc[0][2*np+1], al[0], bh[2], bh[3]);
                    mma16816(acc[1][2*np+1], al[1], bh[2], bh[3]);
                }
            }
        }
    }

#pragma unroll
    for (int mt = 0; mt < 2; mt++) {
        int r0 = wm * 32 + mt * 16 + g;
        float rs0 = 0.f, rs1 = 0.f;
#pragma unroll
        for (int nt = 0; nt < NTILES; nt++) {
            int col = wn * (NT / 2) + nt * 8 + 2 * t;
            float2 lo_pair, hi_pair;
            if (EXP_EPI) {
                lo_pair.x = fast_exp(acc[mt][nt][0]);
                lo_pair.y = fast_exp(acc[mt][nt][1]);
                hi_pair.x = fast_exp(acc[mt][nt][2]);
                hi_pair.y = fast_exp(acc[mt][nt][3]);
                rs0 += lo_pair.x + lo_pair.y;
                rs1 += hi_pair.x + hi_pair.y;
            } else {
                lo_pair.x = acc[mt][nt][0] * alpha;
                lo_pair.y = acc[mt][nt][1] * alpha;
                hi_pair.x = acc[mt][nt][2] * alpha;
                hi_pair.y = acc[mt][nt][3] * alpha;
            }
            *(float2*)(C + (size_t)r0 * ldc + col)       = lo_pair;
            *(float2*)(C + (size_t)(r0 + 8) * ldc + col) = hi_pair;
        }
        if (EXP_EPI) {
            rs0 += __shfl_down_sync(0xffffffffu, rs0, 1, 4);
            rs0 += __shfl_down_sync(0xffffffffu, rs0, 2, 4);
            rs1 += __shfl_down_sync(0xffffffffu, rs1, 1, 4);
            rs1 += __shfl_down_sync(0xffffffffu, rs1, 2, 4);
            if (t == 0) {
                atomicAdd(&rowsum[r0], rs0);
                atomicAdd(&rowsum[r0 + 8], rs1);
            }
        }
    }
}

// ------------------------------- wrappers ----------------------------------
__global__ void __launch_bounds__(256, 2) gemm_hmma_kernel(
    const float* __restrict__ A, const float* __restrict__ B,
    float* __restrict__ C, int N, float alpha)
{
    int m0 = blockIdx.y << 7, n0 = blockIdx.x << 7;
    hmma_core<128, false, 1>(A + (size_t)m0 * DMODEL, DMODEL,
                             B + (size_t)n0 * DMODEL, DMODEL, DMODEL / 32,
                             C + (size_t)m0 * N + n0, (size_t)N, alpha, nullptr);
}

__global__ void __launch_bounds__(256) scores_hmma_kernel()
{
    int bh = blockIdx.z, b = bh >> 4, h = bh & 15;
    int i0 = blockIdx.y << 7, j0 = blockIdx.x << 7;
    const float* Ap = g_q  + ((size_t)(b * NSEQ + i0)) * DMODEL + h * HD;
    const float* Bp = g_kv + ((size_t)(b * NSEQ + j0)) * 2048   + h * HD;
    float* Cb = g_E + (size_t)bh * NSEQ * NSEQ + (size_t)i0 * NSEQ + j0;
    hmma_core<128, true, 3>(Ap, DMODEL, Bp, 2048, HD / 32, Cb, NSEQ, 1.f,
                            g_rowsum + bh * NSEQ + i0);
}

// --------- transpose v: [b][j][c] -> [b][c][j], fp32 -> fp16 ----------------
__global__ void __launch_bounds__(256) transpose_v_kernel()
{
    __shared__ float t[32][33];
    int j0 = blockIdx.x << 5, c0 = blockIdx.y << 5, b = blockIdx.z;
    int tx = threadIdx.x, ty = threadIdx.y;
#pragma unroll
    for (int i = 0; i < 4; i++)
        t[ty + i * 8][tx] =
            g_kv[((size_t)(b * NSEQ) + j0 + ty + i * 8) * 2048 + 1024 + c0 + tx];
    __syncthreads();
#pragma unroll
    for (int i = 0; i < 4; i++)
        g_vth[((size_t)b * DMODEL + c0 + ty + i * 8) * NSEQ + j0 + tx] =
            __float2half(t[tx][ty + i * 8]);
}

// ---- FUSED: softmax-normalize + talking heads + LN + (aw @ v) --------------
// Block = (b, 16-row i-tile), 512 threads = 16 warps. Warp w: phase A row w,
// phase B/C head w. Per 64-j chunk: build fp16 aw[16g][16i][64j] in smem,
// load v tiles, MMA-accumulate out[16i, g*64..] per warp.
__global__ void __launch_bounds__(512, 1) fused_pv_kernel(
    float* __restrict__ out, const float* __restrict__ Wtalk,
    const float* __restrict__ gamma, const float* __restrict__ beta)
{
    extern __shared__ __align__(16) char sm[];
    __half* aw  = (__half*)sm;                         // 16*16*72*2 = 36864 B
    __half* vsm = (__half*)(sm + 36864);               // 16*64*72*2 = 147456 B
    float* wst  = (float*)(sm + 36864 + 147456);       // [h][g] 256 floats
    float* rinv = wst + 256;                           // [h][i] 256 floats
    float* gam  = rinv + 256;
    float* bet  = gam + 16;

    const int tid  = threadIdx.x;
    const int wid  = tid >> 5;
    const int lane = tid & 31;
    const int b  = blockIdx.y;
    const int i0 = blockIdx.x * ITILE;

    if (tid < 256) {
        int h = tid >> 4, g = tid & 15;
        wst[tid] = Wtalk[g * 16 + h];                  // wst[h*16+g]
        rinv[tid] = 1.0f / g_rowsum[(size_t)(b * HN + h) * NSEQ + i0 + g];
        // note: second index of rinv is i (reusing g as i index here)
    }
    if (tid < 16) { gam[tid] = gamma[tid]; bet[tid] = beta[tid]; }
    __syncthreads();

    // ldmatrix base addresses (per warp = head wid)
    const uint32_t awS  = (uint32_t)__cvta_generic_to_shared(aw);
    const uint32_t vsmS = (uint32_t)__cvta_generic_to_shared(vsm);
    const uint32_t aB = awS + (uint32_t)(wid * ITILE * FSTR * 2)
                      + (uint32_t)((lane & 15) * (FSTR * 2) + (lane >> 4) * 16);
    const uint32_t bB = vsmS + (uint32_t)(wid * 64 * FSTR * 2)
                      + (uint32_t)(((lane & 7) + ((lane >> 4) * 8)) * (FSTR * 2)
                                   + ((lane >> 3) & 1) * 16);

    float acc[8][4];
#pragma unroll
    for (int nt = 0; nt < 8; nt++)
#pragma unroll
        for (int q = 0; q < 4; q++) acc[nt][q] = 0.f;

    const int i = wid;                 // phase-A row
    const size_t erow = ((size_t)(b * HN) * NSEQ + (i0 + i)) * NSEQ;
    const __half* vbase = g_vth + ((size_t)b * DMODEL + wid * HD) * NSEQ;

    for (int ch = 0; ch < NSEQ / JCH; ch++) {
        const int j0 = ch * JCH;
        // ---- phase A: talk + LN for (i, j0+2*lane, j0+2*lane+1) -----------
        float2 e[16];
#pragma unroll
        for (int h = 0; h < 16; h++)
            e[h] = *(const float2*)&g_E[erow + (size_t)h * NSEQ * NSEQ
                                        + j0 + 2 * lane];
        float t0[16], t1[16];
#pragma unroll
        for (int g = 0; g < 16; g++) { t0[g] = 0.f; t1[g] = 0.f; }
#pragma unroll
        for (int h = 0; h < 16; h++) {
            float r = rinv[h * 16 + i];
            float p0 = e[h].x * r, p1 = e[h].y * r;
#pragma unroll
            for (int gq = 0; gq < 4; gq++) {
                float4 w4 = *(const float4*)&wst[h * 16 + gq * 4];
                t0[gq*4+0] = fmaf(w4.x, p0, t0[gq*4+0]);
                t1[gq*4+0] = fmaf(w4.x, p1, t1[gq*4+0]);
                t0[gq*4+1] = fmaf(w4.y, p0, t0[gq*4+1]);
                t1[gq*4+1] = fmaf(w4.y, p1, t1[gq*4+1]);
                t0[gq*4+2] = fmaf(w4.z, p0, t0[gq*4+2]);
                t1[gq*4+2] = fmaf(w4.z, p1, t1[gq*4+2]);
                t0[gq*4+3] = fmaf(w4.w, p0, t0[gq*4+3]);
                t1[gq*4+3] = fmaf(w4.w, p1, t1[gq*4+3]);
            }
        }
        float mu0 = 0.f, mu1 = 0.f;
#pragma unroll
        for (int g = 0; g < 16; g++) { mu0 += t0[g]; mu1 += t1[g]; }
        mu0 *= (1.f / 16.f); mu1 *= (1.f / 16.f);
        float v0 = 0.f, v1 = 0.f;
#pragma unroll
        for (int g = 0; g < 16; g++) {
            float d0 = t0[g] - mu0, d1 = t1[g] - mu1;
            v0 = fmaf(d0, d0, v0); v1 = fmaf(d1, d1, v1);
        }
        float rs0 = rsqrtf(v0 * (1.f / 16.f) + LN_EPS);
        float rs1 = rsqrtf(v1 * (1.f / 16.f) + LN_EPS);
#pragma unroll
        for (int g = 0; g < 16; g++) {
            float gg = gam[g], bb = bet[g];
            float a0 = fmaf((t0[g] - mu0) * rs0, gg, bb);
            float a1 = fmaf((t1[g] - mu1) * rs1, gg, bb);
            __half2 hh = __floats2half2_rn(a0, a1);
            *(uint32_t*)&aw[(g * ITILE + i) * FSTR + 2 * lane]
                = *(uint32_t*)&hh;
        }
        // ---- phase B: warp wid loads its v tile [64 d][64 j] --------------
#pragma unroll
        for (int r = 0; r < 16; r++) {
            int lin = r * 32 + lane;
            int d  = lin >> 3;
            int jq = (lin & 7) * 8;
            float4 v4 = *(const float4*)&vbase[(size_t)d * NSEQ + j0 + jq];
            *(float4*)&vsm[(wid * 64 + d) * FSTR + jq] = v4;
        }
        __syncthreads();
        // ---- phase C: MMA  aw[wid] (16x64) @ v[wid]^T (64x64) -------------
#pragma unroll
        for (int ks = 0; ks < 4; ks++) {
            uint32_t a[4];
            ldsm_x4(a, aB + ks * 32);
#pragma unroll
            for (int np = 0; np < 4; np++) {
                uint32_t bb[4];
                ldsm_x4(bb, bB + np * 16 * FSTR * 2 + ks * 32);
                mma16816(acc[2*np],   a, bb[0], bb[1]);
                mma16816(acc[2*np+1], a, bb[2], bb[3]);
            }
        }
        __syncthreads();
    }

    // ---- epilogue: warp wid owns out[i0.., wid*64..] -----------------------
    const int g8 = lane >> 2, tq = lane & 3;
#pragma unroll
    for (int nt = 0; nt < 8; nt++) {
        int col = wid * HD + nt * 8 + 2 * tq;
        *(float2*)&out[(size_t)(b * NSEQ + i0 + g8) * DMODEL + col]
            = make_float2(acc[nt][0], acc[nt][1]);
        *(float2*)&out[(size_t)(b * NSEQ + i0 + g8 + 8) * DMODEL + col]
            = make_float2(acc[nt][2], acc[nt][3]);
    }
}

__global__ void zero_rowsum_kernel()
{
    int i = blockIdx.x * 256 + threadIdx.x;
    if (i < NB * HN * NSEQ) g_rowsum[i] = 0.f;
}

// ---------------------------------------------------------------------------
extern "C" void kernel_launch(void* const* d_in, const int* in_sizes, int n_in,
                              void* d_out, int out_size)
{
    const float* x       = (const float*)d_in[0];
    const float* context = (const float*)d_in[1];
    const float* Wq      = (const float*)d_in[2];
    const float* Wkv     = (const float*)d_in[3];
    const float* Wtalk   = (const float*)d_in[4];
    const float* gamma   = (const float*)d_in[5];
    const float* beta    = (const float*)d_in[6];
    float* out = (float*)d_out;

    float *qp, *kvp;
    cudaGetSymbolAddress((void**)&qp, g_q);
    cudaGetSymbolAddress((void**)&kvp, g_kv);

    const int FUSED_SMEM = 36864 + 147456 + (256 + 256 + 32) * 4;
    cudaFuncSetAttribute(fused_pv_kernel,
                         cudaFuncAttributeMaxDynamicSharedMemorySize, FUSED_SMEM);

    zero_rowsum_kernel<<<(NB * HN * NSEQ + 255) / 256, 256>>>();

    // q = x @ Wq^T (scaled), kv = context @ Wkv^T   (single fp16)
    gemm_hmma_kernel<<<dim3(DMODEL / 128, (NB * NSEQ) / 128), 256>>>(
        x, Wq, qp, DMODEL, 0.125f);
    gemm_hmma_kernel<<<dim3(2048 / 128, (NB * NSEQ) / 128), 256>>>(
        context, Wkv, kvp, 2048, 1.0f);

    // v -> vt (fp16) for the fused PV GEMM
    transpose_v_kernel<<<dim3(NSEQ / 32, DMODEL / 32, NB), dim3(32, 8)>>>();

    // exp(q k^T) per head + row sums   (fp16 split-3, exp-protected)
    scores_hmma_kernel<<<dim3(NSEQ / 128, NSEQ / 128, NB * HN), 256>>>();

    // fused: normalize + talking heads + LN + (aw @ v) -> out
    fused_pv_kernel<<<dim3(NSEQ / ITILE, NB), 512, FUSED_SMEM>>>(
        out, Wtalk, gamma, beta);
}

// round 9
// speedup vs baseline: 1.7254x; 1.1380x over previous
#include <cuda_runtime.h>
#include <cuda_fp16.h>
#include <cstdint>
#include <cstddef>

#define HN     16
#define DMODEL 1024
#define NSEQ   2048
#define NB     2
#define HD     64
#define LN_EPS 1e-5f
#define SSTR   40          // smem stride (halfs) for k=32 tiles
#define FSTR   72          // smem stride (halfs) for k=64 tiles (fused kernel)
#define ITILE  16          // fused kernel i-rows per block
#define JCH    64          // fused kernel j-chunk

typedef unsigned long long u64;

// ---------------- scratch (device globals; no allocation allowed) ----------
__device__ float  g_q [(size_t)NB * NSEQ * DMODEL];
__device__ float  g_kv[(size_t)NB * NSEQ * 2048];
__device__ __half g_vth[(size_t)NB * DMODEL * NSEQ];     // v transposed, fp16
__device__ __half g_E [(size_t)NB * HN * NSEQ * NSEQ];   // exp(scores), fp16
__device__ float  g_rowsum[NB * HN * NSEQ];

// ---------------- fast exp on the FMA pipe (avoid MUFU.EX2) ----------------
__device__ __forceinline__ float fast_exp(float x) {
    float t = x * 1.4426950408889634f;
    float r = rintf(t);
    float f = t - r;
    float p =      1.5403530394e-4f;
    p = fmaf(p, f, 1.3333558146e-3f);
    p = fmaf(p, f, 9.6181291076e-3f);
    p = fmaf(p, f, 5.5504108665e-2f);
    p = fmaf(p, f, 2.4022650696e-1f);
    p = fmaf(p, f, 6.9314718056e-1f);
    p = fmaf(p, f, 1.0f);
    return p * __int_as_float(((int)r + 127) << 23);
}

// ------------------------- mma.sync / ldmatrix ------------------------------
__device__ __forceinline__ void mma16816(
    float (&c)[4], const uint32_t (&a)[4], uint32_t b0, uint32_t b1)
{
    asm volatile(
        "mma.sync.aligned.m16n8k16.row.col.f32.f16.f16.f32 "
        "{%0,%1,%2,%3}, {%4,%5,%6,%7}, {%8,%9}, {%0,%1,%2,%3};"
        : "+f"(c[0]), "+f"(c[1]), "+f"(c[2]), "+f"(c[3])
        : "r"(a[0]), "r"(a[1]), "r"(a[2]), "r"(a[3]), "r"(b0), "r"(b1));
}
__device__ __forceinline__ void ldsm_x4(uint32_t (&r)[4], uint32_t addr) {
    asm volatile("ldmatrix.sync.aligned.m8n8.x4.shared.b16 {%0,%1,%2,%3}, [%4];"
        : "=r"(r[0]), "=r"(r[1]), "=r"(r[2]), "=r"(r[3]) : "r"(addr));
}

// Stage ROWS x 32 fp32 tile as fp16 (optionally hi/lo split), stride SSTR.
template<int ROWS, int SPLIT>
__device__ __forceinline__ void stage_h(
    uint16_t* __restrict__ hi, uint16_t* __restrict__ lo,
    const float* __restrict__ src, size_t stride, int tid)
{
#pragma unroll
    for (int s = 0; s < ROWS / 32; s++) {
        int idx = s * 256 + tid;
        int row = idx >> 3;
        int cg  = idx & 7;
        float4 v = *(const float4*)(src + (size_t)row * stride + cg * 4);
        __half2 h01 = __floats2half2_rn(v.x, v.y);
        __half2 h23 = __floats2half2_rn(v.z, v.w);
        int off = row * SSTR + cg * 4;
        *(uint2*)(hi + off) = make_uint2(*(uint32_t*)&h01, *(uint32_t*)&h23);
        if (SPLIT == 3) {
            float rx = v.x - __half2float(__low2half(h01));
            float ry = v.y - __half2float(__high2half(h01));
            float rz = v.z - __half2float(__low2half(h23));
            float rw = v.w - __half2float(__high2half(h23));
            __half2 l01 = __floats2half2_rn(rx, ry);
            __half2 l23 = __floats2half2_rn(rz, rw);
            *(uint2*)(lo + off) = make_uint2(*(uint32_t*)&l01, *(uint32_t*)&l23);
        }
    }
}

// ---- HMMA fp16 core: C[128 x NT] = A[128,K] @ B[NT,K]^T -------------------
// EXP_EPI: out is fp16 (exp of acc), with fp32 rowsum atomics.
template<int NT, bool EXP_EPI, int SPLIT>
__device__ __forceinline__ void hmma_core(
    const float* __restrict__ A, size_t lda,
    const float* __restrict__ B, size_t ldb,
    int nk, void* __restrict__ Cv, size_t ldc,
    float alpha, float* __restrict__ rowsum)
{
    constexpr int NTILES = NT / 16;
    constexpr int NPAIRS = NTILES / 2;
    __shared__ __align__(16) uint16_t sAhi[128 * SSTR];
    __shared__ __align__(16) uint16_t sAlo[SPLIT == 3 ? 128 * SSTR : 8];
    __shared__ __align__(16) uint16_t sBhi[NT * SSTR];
    __shared__ __align__(16) uint16_t sBlo[SPLIT == 3 ? NT * SSTR : 8];

    const int tid  = threadIdx.x;
    const int wid  = tid >> 5;
    const int lane = tid & 31;
    const int wm = wid & 3, wn = wid >> 2;
    const int g = lane >> 2, t = lane & 3;

    const uint32_t aoff = (uint32_t)((lane & 15) * (SSTR * 2) + (lane >> 4) * 16);
    const uint32_t boff = (uint32_t)(((lane & 7) + ((lane >> 4) * 8)) * (SSTR * 2)
                                     + ((lane >> 3) & 1) * 16);
    const uint32_t aHiB = (uint32_t)__cvta_generic_to_shared(sAhi)
                          + aoff + (uint32_t)(wm * 32 * SSTR * 2);
    const uint32_t aLoB = (uint32_t)__cvta_generic_to_shared(sAlo)
                          + aoff + (uint32_t)(wm * 32 * SSTR * 2);
    const uint32_t bHiB = (uint32_t)__cvta_generic_to_shared(sBhi)
                          + boff + (uint32_t)(wn * (NT / 2) * SSTR * 2);
    const uint32_t bLoB = (uint32_t)__cvta_generic_to_shared(sBlo)
                          + boff + (uint32_t)(wn * (NT / 2) * SSTR * 2);

    float acc[2][NTILES][4];
#pragma unroll
    for (int mt = 0; mt < 2; mt++)
#pragma unroll
        for (int nt = 0; nt < NTILES; nt++)
#pragma unroll
            for (int q = 0; q < 4; q++) acc[mt][nt][q] = 0.f;

    for (int i = 0; i < nk; i++) {
        __syncthreads();
        stage_h<128, SPLIT>(sAhi, sAlo, A + (size_t)i * 32, lda, tid);
        stage_h<NT , SPLIT>(sBhi, sBlo, B + (size_t)i * 32, ldb, tid);
        __syncthreads();
#pragma unroll
        for (int ks = 0; ks < 2; ks++) {
            uint32_t ah[2][4], al[2][4];
            ldsm_x4(ah[0], aHiB + ks * 32);
            ldsm_x4(ah[1], aHiB + 16 * SSTR * 2 + ks * 32);
            if (SPLIT == 3) {
                ldsm_x4(al[0], aLoB + ks * 32);
                ldsm_x4(al[1], aLoB + 16 * SSTR * 2 + ks * 32);
            }
#pragma unroll
            for (int np = 0; np < NPAIRS; np++) {
                uint32_t bh[4];
                ldsm_x4(bh, bHiB + np * 16 * SSTR * 2 + ks * 32);
                mma16816(acc[0][2*np],   ah[0], bh[0], bh[1]);
                mma16816(acc[1][2*np],   ah[1], bh[0], bh[1]);
                mma16816(acc[0][2*np+1], ah[0], bh[2], bh[3]);
                mma16816(acc[1][2*np+1], ah[1], bh[2], bh[3]);
                if (SPLIT == 3) {
                    uint32_t bl[4];
                    ldsm_x4(bl, bLoB + np * 16 * SSTR * 2 + ks * 32);
                    mma16816(acc[0][2*np],   ah[0], bl[0], bl[1]);
                    mma16816(acc[1][2*np],   ah[1], bl[0], bl[1]);
                    mma16816(acc[0][2*np+1], ah[0], bl[2], bl[3]);
                    mma16816(acc[1][2*np+1], ah[1], bl[2], bl[3]);
                    mma16816(acc[0][2*np],   al[0], bh[0], bh[1]);
                    mma16816(acc[1][2*np],   al[1], bh[0], bh[1]);
                    mma16816(acc[0][2*np+1], al[0], bh[2], bh[3]);
                    mma16816(acc[1][2*np+1], al[1], bh[2], bh[3]);
                }
            }
        }
    }

#pragma unroll
    for (int mt = 0; mt < 2; mt++) {
        int r0 = wm * 32 + mt * 16 + g;
        float rs0 = 0.f, rs1 = 0.f;
#pragma unroll
        for (int nt = 0; nt < NTILES; nt++) {
            int col = wn * (NT / 2) + nt * 8 + 2 * t;
            if (EXP_EPI) {
                __half* Ch = (__half*)Cv;
                float e0 = fast_exp(acc[mt][nt][0]);
                float e1 = fast_exp(acc[mt][nt][1]);
                float e2 = fast_exp(acc[mt][nt][2]);
                float e3 = fast_exp(acc[mt][nt][3]);
                rs0 += e0 + e1;
                rs1 += e2 + e3;
                __half2 p01 = __floats2half2_rn(e0, e1);
                __half2 p23 = __floats2half2_rn(e2, e3);
                *(uint32_t*)&Ch[(size_t)r0 * ldc + col]       = *(uint32_t*)&p01;
                *(uint32_t*)&Ch[(size_t)(r0 + 8) * ldc + col] = *(uint32_t*)&p23;
            } else {
                float* C = (float*)Cv;
                float2 lo_pair, hi_pair;
                lo_pair.x = acc[mt][nt][0] * alpha;
                lo_pair.y = acc[mt][nt][1] * alpha;
                hi_pair.x = acc[mt][nt][2] * alpha;
                hi_pair.y = acc[mt][nt][3] * alpha;
                *(float2*)(C + (size_t)r0 * ldc + col)       = lo_pair;
                *(float2*)(C + (size_t)(r0 + 8) * ldc + col) = hi_pair;
            }
        }
        if (EXP_EPI) {
            rs0 += __shfl_down_sync(0xffffffffu, rs0, 1, 4);
            rs0 += __shfl_down_sync(0xffffffffu, rs0, 2, 4);
            rs1 += __shfl_down_sync(0xffffffffu, rs1, 1, 4);
            rs1 += __shfl_down_sync(0xffffffffu, rs1, 2, 4);
            if (t == 0) {
                atomicAdd(&rowsum[r0], rs0);
                atomicAdd(&rowsum[r0 + 8], rs1);
            }
        }
    }
}

// ------------------------------- wrappers ----------------------------------
__global__ void __launch_bounds__(256, 2) gemm_hmma_kernel(
    const float* __restrict__ A, const float* __restrict__ B,
    float* __restrict__ C, int N, float alpha)
{
    int m0 = blockIdx.y << 7, n0 = blockIdx.x << 7;
    hmma_core<128, false, 1>(A + (size_t)m0 * DMODEL, DMODEL,
                             B + (size_t)n0 * DMODEL, DMODEL, DMODEL / 32,
                             C + (size_t)m0 * N + n0, (size_t)N, alpha, nullptr);
}

__global__ void __launch_bounds__(256, 2) scores_hmma_kernel()
{
    int bh = blockIdx.z, b = bh >> 4, h = bh & 15;
    int i0 = blockIdx.y << 7, j0 = blockIdx.x << 7;
    const float* Ap = g_q  + ((size_t)(b * NSEQ + i0)) * DMODEL + h * HD;
    const float* Bp = g_kv + ((size_t)(b * NSEQ + j0)) * 2048   + h * HD;
    __half* Cb = g_E + (size_t)bh * NSEQ * NSEQ + (size_t)i0 * NSEQ + j0;
    hmma_core<128, true, 3>(Ap, DMODEL, Bp, 2048, HD / 32, Cb, NSEQ, 1.f,
                            g_rowsum + bh * NSEQ + i0);
}

// --------- transpose v: [b][j][c] -> [b][c][j], fp32 -> fp16 ----------------
__global__ void __launch_bounds__(256) transpose_v_kernel()
{
    __shared__ float t[32][33];
    int j0 = blockIdx.x << 5, c0 = blockIdx.y << 5, b = blockIdx.z;
    int tx = threadIdx.x, ty = threadIdx.y;
#pragma unroll
    for (int i = 0; i < 4; i++)
        t[ty + i * 8][tx] =
            g_kv[((size_t)(b * NSEQ) + j0 + ty + i * 8) * 2048 + 1024 + c0 + tx];
    __syncthreads();
#pragma unroll
    for (int i = 0; i < 4; i++)
        g_vth[((size_t)b * DMODEL + c0 + ty + i * 8) * NSEQ + j0 + tx] =
            __float2half(t[tx][ty + i * 8]);
}

// ---- FUSED: softmax-normalize + talking heads + LN + (aw @ v) --------------
// Block = (b, 16-row i-tile), 512 threads = 16 warps. Warp w: phase A row w,
// phase B/C head w. E is fp16; next chunk's E prefetched into regs during MMA.
__global__ void __launch_bounds__(512, 1) fused_pv_kernel(
    float* __restrict__ out, const float* __restrict__ Wtalk,
    const float* __restrict__ gamma, const float* __restrict__ beta)
{
    extern __shared__ __align__(16) char sm[];
    __half* aw  = (__half*)sm;                         // 16*16*72*2 = 36864 B
    __half* vsm = (__half*)(sm + 36864);               // 16*64*72*2 = 147456 B
    float* wst  = (float*)(sm + 36864 + 147456);       // [h][g] 256 floats
    float* rinv = wst + 256;                           // [h][i] 256 floats
    float* gam  = rinv + 256;
    float* bet  = gam + 16;

    const int tid  = threadIdx.x;
    const int wid  = tid >> 5;
    const int lane = tid & 31;
    const int b  = blockIdx.y;
    const int i0 = blockIdx.x * ITILE;

    if (tid < 256) {
        int h = tid >> 4, g = tid & 15;
        wst[tid] = Wtalk[g * 16 + h];                  // wst[h*16+g]
        rinv[tid] = 1.0f / g_rowsum[(size_t)(b * HN + h) * NSEQ + i0 + g];
    }
    if (tid < 16) { gam[tid] = gamma[tid]; bet[tid] = beta[tid]; }
    __syncthreads();

    const uint32_t awS  = (uint32_t)__cvta_generic_to_shared(aw);
    const uint32_t vsmS = (uint32_t)__cvta_generic_to_shared(vsm);
    const uint32_t aB = awS + (uint32_t)(wid * ITILE * FSTR * 2)
                      + (uint32_t)((lane & 15) * (FSTR * 2) + (lane >> 4) * 16);
    const uint32_t bB = vsmS + (uint32_t)(wid * 64 * FSTR * 2)
                      + (uint32_t)(((lane & 7) + ((lane >> 4) * 8)) * (FSTR * 2)
                                   + ((lane >> 3) & 1) * 16);

    float acc[8][4];
#pragma unroll
    for (int nt = 0; nt < 8; nt++)
#pragma unroll
        for (int q = 0; q < 4; q++) acc[nt][q] = 0.f;

    const int i = wid;                 // phase-A row
    const size_t erow = ((size_t)(b * HN) * NSEQ + (i0 + i)) * NSEQ + 2 * lane;
    const size_t PL = (size_t)NSEQ * NSEQ;
    const __half* vbase = g_vth + ((size_t)b * DMODEL + wid * HD) * NSEQ;

    uint32_t eraw[16];
#pragma unroll
    for (int h = 0; h < 16; h++)
        eraw[h] = *(const uint32_t*)&g_E[erow + (size_t)h * PL];

    for (int ch = 0; ch < NSEQ / JCH; ch++) {
        const int j0 = ch * JCH;
        // ---- phase A: talk + LN for (i, j0+2*lane, j0+2*lane+1) -----------
        float t0[16], t1[16];
#pragma unroll
        for (int g = 0; g < 16; g++) { t0[g] = 0.f; t1[g] = 0.f; }
#pragma unroll
        for (int h = 0; h < 16; h++) {
            float2 ef = __half22float2(*(__half2*)&eraw[h]);
            float r = rinv[h * 16 + i];
            float p0 = ef.x * r, p1 = ef.y * r;
#pragma unroll
            for (int gq = 0; gq < 4; gq++) {
                float4 w4 = *(const float4*)&wst[h * 16 + gq * 4];
                t0[gq*4+0] = fmaf(w4.x, p0, t0[gq*4+0]);
                t1[gq*4+0] = fmaf(w4.x, p1, t1[gq*4+0]);
                t0[gq*4+1] = fmaf(w4.y, p0, t0[gq*4+1]);
                t1[gq*4+1] = fmaf(w4.y, p1, t1[gq*4+1]);
                t0[gq*4+2] = fmaf(w4.z, p0, t0[gq*4+2]);
                t1[gq*4+2] = fmaf(w4.z, p1, t1[gq*4+2]);
                t0[gq*4+3] = fmaf(w4.w, p0, t0[gq*4+3]);
                t1[gq*4+3] = fmaf(w4.w, p1, t1[gq*4+3]);
            }
        }
        float mu0 = 0.f, mu1 = 0.f;
#pragma unroll
        for (int g = 0; g < 16; g++) { mu0 += t0[g]; mu1 += t1[g]; }
        mu0 *= (1.f / 16.f); mu1 *= (1.f / 16.f);
        float v0 = 0.f, v1 = 0.f;
#pragma unroll
        for (int g = 0; g < 16; g++) {
            float d0 = t0[g] - mu0, d1 = t1[g] - mu1;
            v0 = fmaf(d0, d0, v0); v1 = fmaf(d1, d1, v1);
        }
        float rs0 = rsqrtf(v0 * (1.f / 16.f) + LN_EPS);
        float rs1 = rsqrtf(v1 * (1.f / 16.f) + LN_EPS);
#pragma unroll
        for (int g = 0; g < 16; g++) {
            float gg = gam[g], bb = bet[g];
            float a0 = fmaf((t0[g] - mu0) * rs0, gg, bb);
            float a1 = fmaf((t1[g] - mu1) * rs1, gg, bb);
            __half2 hh = __floats2half2_rn(a0, a1);
            *(uint32_t*)&aw[(g * ITILE + i) * FSTR + 2 * lane]
                = *(uint32_t*)&hh;
        }
        // ---- phase B: warp wid loads its v tile [64 d][64 j] --------------
#pragma unroll
        for (int r = 0; r < 16; r++) {
            int lin = r * 32 + lane;
            int d  = lin >> 3;
            int jq = (lin & 7) * 8;
            float4 v4 = *(const float4*)&vbase[(size_t)d * NSEQ + j0 + jq];
            *(float4*)&vsm[(wid * 64 + d) * FSTR + jq] = v4;
        }
        __syncthreads();
        // ---- prefetch next chunk's E into regs (hidden under MMAs) --------
        if (ch + 1 < NSEQ / JCH) {
#pragma unroll
            for (int h = 0; h < 16; h++)
                eraw[h] = *(const uint32_t*)&g_E[erow + (size_t)h * PL
                                                 + (j0 + JCH)];
        }
        // ---- phase C: MMA  aw[wid] (16x64) @ v[wid]^T (64x64) -------------
#pragma unroll
        for (int ks = 0; ks < 4; ks++) {
            uint32_t a[4];
            ldsm_x4(a, aB + ks * 32);
#pragma unroll
            for (int np = 0; np < 4; np++) {
                uint32_t bb[4];
                ldsm_x4(bb, bB + np * 16 * FSTR * 2 + ks * 32);
                mma16816(acc[2*np],   a, bb[0], bb[1]);
                mma16816(acc[2*np+1], a, bb[2], bb[3]);
            }
        }
        __syncthreads();
    }

    // ---- epilogue: warp wid owns out[i0.., wid*64..] -----------------------
    const int g8 = lane >> 2, tq = lane & 3;
#pragma unroll
    for (int nt = 0; nt < 8; nt++) {
        int col = wid * HD + nt * 8 + 2 * tq;
        *(float2*)&out[(size_t)(b * NSEQ + i0 + g8) * DMODEL + col]
            = make_float2(acc[nt][0], acc[nt][1]);
        *(float2*)&out[(size_t)(b * NSEQ + i0 + g8 + 8) * DMODEL + col]
            = make_float2(acc[nt][2], acc[nt][3]);
    }
}

__global__ void zero_rowsum_kernel()
{
    int i = blockIdx.x * 256 + threadIdx.x;
    if (i < NB * HN * NSEQ) g_rowsum[i] = 0.f;
}

// ---------------------------------------------------------------------------
extern "C" void kernel_launch(void* const* d_in, const int* in_sizes, int n_in,
                              void* d_out, int out_size)
{
    const float* x       = (const float*)d_in[0];
    const float* context = (const float*)d_in[1];
    const float* Wq      = (const float*)d_in[2];
    const float* Wkv     = (const float*)d_in[3];
    const float* Wtalk   = (const float*)d_in[4];
    const float* gamma   = (const float*)d_in[5];
    const float* beta    = (const float*)d_in[6];
    float* out = (float*)d_out;

    float *qp, *kvp;
    cudaGetSymbolAddress((void**)&qp, g_q);
    cudaGetSymbolAddress((void**)&kvp, g_kv);

    const int FUSED_SMEM = 36864 + 147456 + (256 + 256 + 32) * 4;
    cudaFuncSetAttribute(fused_pv_kernel,
                         cudaFuncAttributeMaxDynamicSharedMemorySize, FUSED_SMEM);

    zero_rowsum_kernel<<<(NB * HN * NSEQ + 255) / 256, 256>>>();

    // q = x @ Wq^T (scaled), kv = context @ Wkv^T   (single fp16)
    gemm_hmma_kernel<<<dim3(DMODEL / 128, (NB * NSEQ) / 128), 256>>>(
        x, Wq, qp, DMODEL, 0.125f);
    gemm_hmma_kernel<<<dim3(2048 / 128, (NB * NSEQ) / 128), 256>>>(
        context, Wkv, kvp, 2048, 1.0f);

    // v -> vt (fp16) for the fused PV GEMM
    transpose_v_kernel<<<dim3(NSEQ / 32, DMODEL / 32, NB), dim3(32, 8)>>>();

    // exp(q k^T) per head + row sums   (fp16 split-3, fp16 E out)
    scores_hmma_kernel<<<dim3(NSEQ / 128, NSEQ / 128, NB * HN), 256>>>();

    // fused: normalize + talking heads + LN + (aw @ v) -> out
    fused_pv_kernel<<<dim3(NSEQ / ITILE, NB), 512, FUSED_SMEM>>>(
        out, Wtalk, gamma, beta);
}